// round 7
// baseline (speedup 1.0000x reference)
#include <cuda_runtime.h>
#include <cuda_fp16.h>
#include <cstdint>

#define B 32
#define K 1024
#define F 128
#define E 128
#define OUT2 125
#define ALPHA 0.2f

#define CH 64                  // j/k chunk width
#define NCH3 (K / CH)          // 16
#define EPITCH 1032            // E cache pitch (floats) -> 4128 B rows
#define APH 72                 // k3f A-tile pitch (halves), 144 B
#define ABUF (32 * APH * 2)    // 4608 B
#define XPH 136                // X/B-tile pitch (halves), 272 B
#define XBUF (CH * XPH * 2)    // 17408 B
#define PPH 72                 // k4 A-tile pitch (halves)
#define PBUF (128 * PPH * 2)   // 18432 B
#define NSPLIT 4

// k3f smem offsets (bytes)
#define OFF_S2 0
#define OFF_S1 4096
#define OFF_INV 4224
#define OFF_E 4352
#define OFF_A (OFF_E + 32 * EPITCH * 4)   // 136448
#define OFF_X (OFF_A + 2 * ABUF)          // 145664
#define SMEM_K3F (OFF_X + 2 * XBUF)       // 180480
#define SMEM_K4 (2 * (PBUF + XBUF))       // 71680

// -------------------- scratch (device globals, allocation-free) ------------
__device__ float g_w1[F];
__device__ float g_w2[F];
__device__ float g_c[2];
__device__ float g_s1[B * K];
__device__ float g_s2[B * K];
__device__ __half g_xh[(size_t)B * K * F];             // fp16 x
__device__ __half g_wh[128 * K];                       // fp16 lin2_w (o padded)
__device__ __half g_hh[(size_t)B * K * F];             // fp16 h
__device__ float g_h2p[NSPLIT][(size_t)B * F * OUT2];  // partials

__device__ __forceinline__ uint32_t smem_u32(const void* p) {
    uint32_t a;
    asm("{ .reg .u64 t; cvta.to.shared.u64 t, %1; cvt.u32.u64 %0, t; }" : "=r"(a) : "l"(p));
    return a;
}
__device__ __forceinline__ void cp16(uint32_t dst, const void* src) {
    asm volatile("cp.async.cg.shared.global [%0], [%1], 16;" :: "r"(dst), "l"(src) : "memory");
}
__device__ __forceinline__ void cp16z(uint32_t dst, const void* src, int bytes) {
    asm volatile("cp.async.cg.shared.global [%0], [%1], 16, %2;"
                 :: "r"(dst), "l"(src), "r"(bytes) : "memory");
}
__device__ __forceinline__ void cp_commit() {
    asm volatile("cp.async.commit_group;" ::: "memory");
}
#define CP_WAIT(n) asm volatile("cp.async.wait_group %0;" :: "n"(n) : "memory")

__device__ __forceinline__ void ldsm4(uint32_t* r, uint32_t addr) {
    asm volatile("ldmatrix.sync.aligned.m8n8.x4.shared.b16 {%0,%1,%2,%3}, [%4];"
                 : "=r"(r[0]), "=r"(r[1]), "=r"(r[2]), "=r"(r[3]) : "r"(addr));
}
__device__ __forceinline__ void ldsm4t(uint32_t* r, uint32_t addr) {
    asm volatile("ldmatrix.sync.aligned.m8n8.x4.trans.shared.b16 {%0,%1,%2,%3}, [%4];"
                 : "=r"(r[0]), "=r"(r[1]), "=r"(r[2]), "=r"(r[3]) : "r"(addr));
}
#define MMA_F16(acc, a, b0, b1)                                            \
    asm volatile(                                                          \
        "mma.sync.aligned.m16n8k16.row.col.f32.f16.f16.f32 "               \
        "{%0,%1,%2,%3}, {%4,%5,%6,%7}, {%8,%9}, {%0,%1,%2,%3};"            \
        : "+f"((acc)[0]), "+f"((acc)[1]), "+f"((acc)[2]), "+f"((acc)[3])   \
        : "r"((a)[0]), "r"((a)[1]), "r"((a)[2]), "r"((a)[3]),              \
          "r"(b0), "r"(b1))

// ---------------------------------------------------------------------------
// k1: fold a: w1 = lin_w^T a1, c1 = lin_b.a1 (and 2)
// ---------------------------------------------------------------------------
__global__ void k1_prep(const float* __restrict__ lin_w,
                        const float* __restrict__ lin_b,
                        const float* __restrict__ a) {
    int f = threadIdx.x;
    __shared__ float sa1[E], sa2[E], red1[E], red2[E];
    float a1v = a[f], a2v = a[E + f];
    sa1[f] = a1v;
    sa2[f] = a2v;
    __syncthreads();
    float acc1 = 0.f, acc2 = 0.f;
#pragma unroll 8
    for (int e = 0; e < E; e++) {
        float lw = lin_w[e * F + f];
        acc1 += lw * sa1[e];
        acc2 += lw * sa2[e];
    }
    g_w1[f] = acc1;
    g_w2[f] = acc2;
    float lb = lin_b[f];
    red1[f] = lb * a1v;
    red2[f] = lb * a2v;
    __syncthreads();
    for (int s = 64; s > 0; s >>= 1) {
        if (f < s) {
            red1[f] += red1[f + s];
            red2[f] += red2[f + s];
        }
        __syncthreads();
    }
    if (f == 0) {
        g_c[0] = red1[0];
        g_c[1] = red2[0];
    }
}

// ---------------------------------------------------------------------------
// k2: s1/s2 row scores (exact fp32). One warp per row.
// ---------------------------------------------------------------------------
__global__ void k2_scores(const float* __restrict__ x) {
    int row = (blockIdx.x * blockDim.x + threadIdx.x) >> 5;
    int lane = threadIdx.x & 31;
    if (row >= B * K) return;
    float4 xv = ((const float4*)(x + (size_t)row * F))[lane];
    float4 w1 = ((const float4*)g_w1)[lane];
    float4 w2 = ((const float4*)g_w2)[lane];
    float d1 = xv.x * w1.x + xv.y * w1.y + xv.z * w1.z + xv.w * w1.w;
    float d2 = xv.x * w2.x + xv.y * w2.y + xv.z * w2.z + xv.w * w2.w;
#pragma unroll
    for (int off = 16; off; off >>= 1) {
        d1 += __shfl_xor_sync(~0u, d1, off);
        d2 += __shfl_xor_sync(~0u, d2, off);
    }
    if (lane == 0) {
        g_s1[row] = d1 + g_c[0];
        g_s2[row] = d2 + g_c[1];
    }
}

// ---------------------------------------------------------------------------
// k2h: fp32 -> fp16 conversion, 8 elems/thread.
// ---------------------------------------------------------------------------
__global__ void k2h_half(const float* __restrict__ src, __half* __restrict__ dst, int n8) {
    int i = blockIdx.x * 256 + threadIdx.x;
    if (i >= n8) return;
    float4 a = ((const float4*)src)[2 * i];
    float4 b = ((const float4*)src)[2 * i + 1];
    __half2 h[4];
    h[0] = __floats2half2_rn(a.x, a.y);
    h[1] = __floats2half2_rn(a.z, a.w);
    h[2] = __floats2half2_rn(b.x, b.y);
    h[3] = __floats2half2_rn(b.z, b.w);
    ((uint4*)dst)[i] = *(uint4*)h;
}

// ---------------------------------------------------------------------------
// k3f: one-pass fused softmax + GEMM per (b, 32 i-rows).
//  - compute unnormalized E = exp(leaky(s1+s2)+bias) once -> fp32 smem cache,
//    row sums in registers (warp-per-row, coalesced)
//  - per 64-chunk: E -> fp16 A-tile, cp.async X tile, m16n8k16 MMA
//  - attn = E * inv streamed from smem (coalesced float4)
//  - epilogue: h = acc*inv + x
// ---------------------------------------------------------------------------
__global__ void __launch_bounds__(256, 1) k3f(const float* __restrict__ x,
                                              const float* __restrict__ bias,
                                              float* __restrict__ attn) {
    extern __shared__ char sm[];
    const uint32_t sbase = smem_u32(sm);
    float* s2s = (float*)(sm + OFF_S2);
    float* s1s = (float*)(sm + OFF_S1);
    float* invs = (float*)(sm + OFF_INV);
    float* Es = (float*)(sm + OFF_E);

    const int tid = threadIdx.x;
    const int wid = tid >> 5, lane = tid & 31;
    const int b = blockIdx.y;
    const int i0 = blockIdx.x * 32;
    const int warp_m = (wid >> 2) * 16;  // 0 or 16
    const int warp_n = (wid & 3) * 32;   // 0..96
    const int qr = lane >> 2, qc = lane & 3;
    const int lrow = (lane & 7) | (((lane >> 3) & 1) << 3);
    const int lhi = (lane >> 4) * 8;

    const __half* Xh = g_xh + (size_t)b * K * F;
    const int jx = tid >> 2, cx = tid & 3;  // X staging coords

    for (int j = tid; j < K; j += 256) s2s[j] = g_s2[b * K + j];
    if (tid < 32) s1s[tid] = g_s1[b * K + i0 + tid];
    __syncthreads();

    float s1v[4], sums[4];
#pragma unroll
    for (int r = 0; r < 4; r++) {
        s1v[r] = s1s[wid * 4 + r];
        sums[r] = 0.f;
    }

    float acc[4][4];
#pragma unroll
    for (int nt = 0; nt < 4; nt++)
#pragma unroll
        for (int q = 0; q < 4; q++) acc[nt][q] = 0.f;

#define STAGE_X(c, bi)                                                          \
    do {                                                                        \
        uint32_t xd = sbase + OFF_X + (bi) * XBUF;                              \
        _Pragma("unroll") for (int t = 0; t < 4; t++) {                         \
            int col = cx + t * 4;                                              \
            cp16(xd + jx * (XPH * 2) + col * 16,                                \
                 Xh + (size_t)((c) * CH + jx) * F + col * 8);                   \
        }                                                                       \
        cp_commit();                                                            \
    } while (0)

    STAGE_X(0, 0);

    for (int c = 0; c < NCH3; c++) {
        int bi = c & 1;
        // ---- compute E chunk (warp-per-row, coalesced float2) ----
#pragma unroll
        for (int r = 0; r < 4; r++) {
            int row = wid * 4 + r;
            float2 bv = *(const float2*)(bias + (size_t)(i0 + row) * K + c * CH + lane * 2);
            float2 s2v = *(const float2*)(s2s + c * CH + lane * 2);
            float v0 = s1v[r] + s2v.x;
            v0 = (v0 > 0.f ? v0 : ALPHA * v0) + bv.x;
            float v1 = s1v[r] + s2v.y;
            v1 = (v1 > 0.f ? v1 : ALPHA * v1) + bv.y;
            float e0 = __expf(v0), e1 = __expf(v1);
            *(float2*)(Es + (size_t)row * EPITCH + c * CH + lane * 2) = make_float2(e0, e1);
            sums[r] += e0 + e1;
        }
        __syncthreads();
        if (c + 1 < NCH3) STAGE_X(c + 1, bi ^ 1);
        // ---- convert E chunk -> fp16 A-tile ----
        {
            int arow = tid >> 3, jb = (tid & 7) * 8;
            const float* esrc = Es + (size_t)arow * EPITCH + c * CH + jb;
            float4 e0 = *(const float4*)esrc;
            float4 e1 = *(const float4*)(esrc + 4);
            __half2 hh[4];
            hh[0] = __floats2half2_rn(e0.x, e0.y);
            hh[1] = __floats2half2_rn(e0.z, e0.w);
            hh[2] = __floats2half2_rn(e1.x, e1.y);
            hh[3] = __floats2half2_rn(e1.z, e1.w);
            *(uint4*)(sm + OFF_A + bi * ABUF + arow * (APH * 2) + jb * 2) = *(uint4*)hh;
        }
        if (c + 1 < NCH3) {
            CP_WAIT(1);
        } else {
            CP_WAIT(0);
        }
        __syncthreads();
        // ---- MMA ----
        uint32_t pA = sbase + OFF_A + bi * ABUF + (warp_m + lrow) * (APH * 2) + lhi * 2;
        uint32_t pB = sbase + OFF_X + bi * XBUF + lrow * (XPH * 2) + (warp_n + lhi) * 2;
#pragma unroll
        for (int kk = 0; kk < 4; kk++) {
            uint32_t af[4];
            ldsm4(af, pA + kk * 32);
            uint32_t bf[2][4];
            ldsm4t(bf[0], pB + kk * 16 * (XPH * 2));
            ldsm4t(bf[1], pB + kk * 16 * (XPH * 2) + 32);
            MMA_F16(acc[0], af, bf[0][0], bf[0][1]);
            MMA_F16(acc[1], af, bf[0][2], bf[0][3]);
            MMA_F16(acc[2], af, bf[1][0], bf[1][1]);
            MMA_F16(acc[3], af, bf[1][2], bf[1][3]);
        }
    }

    // ---- row-sum reduction -> inv ----
#pragma unroll
    for (int r = 0; r < 4; r++) {
#pragma unroll
        for (int off = 16; off; off >>= 1) sums[r] += __shfl_xor_sync(~0u, sums[r], off);
    }
    if (lane == 0) {
#pragma unroll
        for (int r = 0; r < 4; r++) invs[wid * 4 + r] = 1.0f / sums[r];
    }
    __syncthreads();

    // ---- attention write: attn = E * inv (coalesced) ----
#pragma unroll
    for (int r = 0; r < 4; r++) {
        int row = wid * 4 + r;
        float iv = 1.0f / sums[r];  // all lanes hold reduced sum
        const float4* esrc = (const float4*)(Es + (size_t)row * EPITCH);
        float4* arow = (float4*)(attn + ((size_t)(b * K + i0 + row)) * K);
#pragma unroll
        for (int t = 0; t < 8; t++) {
            int j4 = lane + t * 32;
            float4 e = esrc[j4];
            e.x *= iv; e.y *= iv; e.z *= iv; e.w *= iv;
            arow[j4] = e;
        }
    }

    // ---- epilogue: h = acc*inv + x ----
    {
        float ivA = invs[warp_m + qr];
        float ivB = invs[warp_m + qr + 8];
        int r0 = i0 + warp_m + qr;
        const float* Xb = x + (size_t)b * K * F;
#pragma unroll
        for (int nt = 0; nt < 4; nt++) {
            int fc = warp_n + nt * 8 + qc * 2;
            float2 xv0 = *(const float2*)(Xb + (size_t)r0 * F + fc);
            float2 xv1 = *(const float2*)(Xb + (size_t)(r0 + 8) * F + fc);
            *(__half2*)(g_hh + ((size_t)b * K + r0) * F + fc) =
                __floats2half2_rn(acc[nt][0] * ivA + xv0.x, acc[nt][1] * ivA + xv0.y);
            *(__half2*)(g_hh + ((size_t)b * K + r0 + 8) * F + fc) =
                __floats2half2_rn(acc[nt][2] * ivB + xv1.x, acc[nt][3] * ivB + xv1.y);
        }
    }
}

// ---------------------------------------------------------------------------
// k4: h2 partial via fp16 mma. A = g_wh [o x k], B = g_hh [k x f].
// ---------------------------------------------------------------------------
__global__ void __launch_bounds__(256, 2) k4_lin2() {
    extern __shared__ char sm[];
    const uint32_t sbase = smem_u32(sm);
    const int tid = threadIdx.x;
    const int wid = tid >> 5, lane = tid & 31;
    const int b = blockIdx.x;
    const int ks = blockIdx.y;
    const int k0 = ks * (K / NSPLIT);
    const int warp_m = (wid >> 2) * 64;
    const int warp_n = (wid & 3) * 32;
    const int qr = lane >> 2, qc = lane & 3;

    const __half* Hb = g_hh + (size_t)b * K * F;
    const int rw = tid >> 1, cw = tid & 1;
    const int jx = tid >> 2, cx = tid & 3;
    const int lrow = (lane & 7) | (((lane >> 3) & 1) << 3);
    const int lhi = (lane >> 4) * 8;

    float acc[4][4][4];
#pragma unroll
    for (int mt = 0; mt < 4; mt++)
#pragma unroll
        for (int nt = 0; nt < 4; nt++)
#pragma unroll
            for (int q = 0; q < 4; q++) acc[mt][nt][q] = 0.f;

#define STAGE4(c, bi)                                                                 \
    do {                                                                              \
        uint32_t ad = sbase + (bi) * PBUF;                                            \
        uint32_t bd = sbase + 2 * PBUF + (bi) * XBUF;                                 \
        int vb = rw < OUT2 ? 16 : 0;                                                  \
        const __half* wsrc = g_wh + (size_t)(rw < OUT2 ? rw : 0) * K + k0 + (c) * CH; \
        _Pragma("unroll") for (int t = 0; t < 4; t++) {                               \
            int col = cw * 4 + t;                                                     \
            cp16z(ad + rw * (PPH * 2) + col * 16, wsrc + col * 8, vb);                \
        }                                                                             \
        _Pragma("unroll") for (int t = 0; t < 4; t++) {                               \
            int col = cx + t * 4;                                                     \
            cp16(bd + jx * (XPH * 2) + col * 16,                                      \
                 Hb + (size_t)(k0 + (c) * CH + jx) * F + col * 8);                    \
        }                                                                             \
        cp_commit();                                                                  \
    } while (0)

    const int NCH4 = (K / NSPLIT) / CH;  // 4
    STAGE4(0, 0);
    for (int c = 0; c < NCH4; c++) {
        int bi = c & 1;
        if (c + 1 < NCH4) {
            STAGE4(c + 1, bi ^ 1);
            CP_WAIT(1);
        } else {
            CP_WAIT(0);
        }
        __syncthreads();
        uint32_t pA = sbase + bi * PBUF + (warp_m + lrow) * (PPH * 2) + lhi * 2;
        uint32_t pB = sbase + 2 * PBUF + bi * XBUF + lrow * (XPH * 2) + (warp_n + lhi) * 2;
#pragma unroll
        for (int kk = 0; kk < 4; kk++) {
            uint32_t af[4][4];
#pragma unroll
            for (int mt = 0; mt < 4; mt++)
                ldsm4(af[mt], pA + mt * 16 * (PPH * 2) + kk * 32);
            uint32_t bf[2][4];
#pragma unroll
            for (int ntp = 0; ntp < 2; ntp++)
                ldsm4t(bf[ntp], pB + kk * 16 * (XPH * 2) + ntp * 32);
#pragma unroll
            for (int mt = 0; mt < 4; mt++)
#pragma unroll
                for (int ntp = 0; ntp < 2; ntp++) {
                    MMA_F16(acc[mt][2 * ntp], af[mt], bf[ntp][0], bf[ntp][1]);
                    MMA_F16(acc[mt][2 * ntp + 1], af[mt], bf[ntp][2], bf[ntp][3]);
                }
        }
        __syncthreads();
    }

    float* out = g_h2p[ks] + (size_t)b * F * OUT2;
#pragma unroll
    for (int mt = 0; mt < 4; mt++) {
        int o0 = warp_m + mt * 16 + qr;
#pragma unroll
        for (int nt = 0; nt < 4; nt++) {
            int fc = warp_n + nt * 8 + qc * 2;
            if (o0 < OUT2) {
                out[(size_t)fc * OUT2 + o0] = acc[mt][nt][0];
                out[(size_t)(fc + 1) * OUT2 + o0] = acc[mt][nt][1];
            }
            if (o0 + 8 < OUT2) {
                out[(size_t)fc * OUT2 + o0 + 8] = acc[mt][nt][2];
                out[(size_t)(fc + 1) * OUT2 + o0 + 8] = acc[mt][nt][3];
            }
        }
    }
}

// ---------------------------------------------------------------------------
// k5: out = relu(sum partials + lin2_b)
// ---------------------------------------------------------------------------
__global__ void k5_out(const float* __restrict__ lin2_b, float* __restrict__ out) {
    int i = blockIdx.x * 256 + threadIdx.x;
    if (i >= B * F * OUT2) return;
    float v = lin2_b[i % OUT2];
#pragma unroll
    for (int p = 0; p < NSPLIT; p++) v += g_h2p[p][i];
    out[i] = v > 0.f ? v : 0.f;
}

// ---------------------------------------------------------------------------
extern "C" void kernel_launch(void* const* d_in, const int* in_sizes, int n_in,
                              void* d_out, int out_size) {
    const float* x      = (const float*)d_in[0];
    const float* lin_w  = (const float*)d_in[1];
    const float* lin_b  = (const float*)d_in[2];
    const float* a      = (const float*)d_in[3];
    const float* bias   = (const float*)d_in[4];
    const float* lin2_w = (const float*)d_in[5];
    const float* lin2_b = (const float*)d_in[6];
    float* out = (float*)d_out;
    float* out_h2 = out;                           // (B,F,OUT2)
    float* out_attn = out + (size_t)B * F * OUT2;  // (B,K,K)

    cudaFuncSetAttribute(k3f, cudaFuncAttributeMaxDynamicSharedMemorySize, SMEM_K3F);
    cudaFuncSetAttribute(k4_lin2, cudaFuncAttributeMaxDynamicSharedMemorySize, SMEM_K4);

    void* xh = nullptr;
    void* wh = nullptr;
    cudaGetSymbolAddress(&xh, g_xh);
    cudaGetSymbolAddress(&wh, g_wh);

    k1_prep<<<1, 128>>>(lin_w, lin_b, a);
    k2_scores<<<(B * K) / 8, 256>>>(x);
    k2h_half<<<(B * K * F / 8 + 255) / 256, 256>>>(x, (__half*)xh, B * K * F / 8);
    k2h_half<<<(OUT2 * K / 8 + 255) / 256, 256>>>(lin2_w, (__half*)wh, OUT2 * K / 8);
    k3f<<<dim3(K / 32, B), 256, SMEM_K3F>>>(x, bias, out_attn);
    k4_lin2<<<dim3(B, NSPLIT), 256, SMEM_K4>>>();
    k5_out<<<(B * F * OUT2 + 255) / 256, 256>>>(lin2_b, out_h2);
}

// round 9
// speedup vs baseline: 1.4238x; 1.4238x over previous
#include <cuda_runtime.h>
#include <cuda_fp16.h>
#include <cstdint>

#define B 32
#define K 1024
#define F 128
#define E 128
#define OUT2 125
#define ALPHA 0.2f

#define CH 64                 // j/k chunk width
#define NCH3 (K / CH)         // 16
#define APH 72                // A-tile pitch (halves), 144 B
#define ABUF (128 * APH * 2)  // 18432 B
#define XPH 136               // B-tile pitch (halves), 272 B
#define XBUF (CH * XPH * 2)   // 17408 B
#define NSPLIT 4

// k3g smem offsets (bytes)
#define OFF_S2 0
#define OFF_S1 4096
#define OFF_INV 4608
#define OFF_A 5120
#define OFF_X (OFF_A + 2 * ABUF)     // 41984
#define SMEM_K3G (OFF_X + 2 * XBUF)  // 76800
#define SMEM_K4 (2 * (ABUF + XBUF))  // 71680

// -------------------- scratch (device globals, allocation-free) ------------
__device__ float g_w1[F];
__device__ float g_w2[F];
__device__ float g_c[2];
__device__ float g_s1[B * K];
__device__ float g_s2[B * K];
__device__ float g_inv[B * K];
__device__ __half g_xh[(size_t)B * K * F];             // fp16 x
__device__ __half g_wh[128 * K];                       // fp16 lin2_w (o padded)
__device__ __half g_hh[(size_t)B * K * F];             // fp16 h
__device__ float g_h2p[NSPLIT][(size_t)B * F * OUT2];  // partials

__device__ __forceinline__ uint32_t smem_u32(const void* p) {
    uint32_t a;
    asm("{ .reg .u64 t; cvta.to.shared.u64 t, %1; cvt.u32.u64 %0, t; }" : "=r"(a) : "l"(p));
    return a;
}
__device__ __forceinline__ void cp16(uint32_t dst, const void* src) {
    asm volatile("cp.async.cg.shared.global [%0], [%1], 16;" :: "r"(dst), "l"(src) : "memory");
}
__device__ __forceinline__ void cp16z(uint32_t dst, const void* src, int bytes) {
    asm volatile("cp.async.cg.shared.global [%0], [%1], 16, %2;"
                 :: "r"(dst), "l"(src), "r"(bytes) : "memory");
}
__device__ __forceinline__ void cp_commit() {
    asm volatile("cp.async.commit_group;" ::: "memory");
}
#define CP_WAIT(n) asm volatile("cp.async.wait_group %0;" :: "n"(n) : "memory")

__device__ __forceinline__ void ldsm4(uint32_t* r, uint32_t addr) {
    asm volatile("ldmatrix.sync.aligned.m8n8.x4.shared.b16 {%0,%1,%2,%3}, [%4];"
                 : "=r"(r[0]), "=r"(r[1]), "=r"(r[2]), "=r"(r[3]) : "r"(addr));
}
__device__ __forceinline__ void ldsm4t(uint32_t* r, uint32_t addr) {
    asm volatile("ldmatrix.sync.aligned.m8n8.x4.trans.shared.b16 {%0,%1,%2,%3}, [%4];"
                 : "=r"(r[0]), "=r"(r[1]), "=r"(r[2]), "=r"(r[3]) : "r"(addr));
}
#define MMA_F16(acc, a, b0, b1)                                            \
    asm volatile(                                                          \
        "mma.sync.aligned.m16n8k16.row.col.f32.f16.f16.f32 "               \
        "{%0,%1,%2,%3}, {%4,%5,%6,%7}, {%8,%9}, {%0,%1,%2,%3};"            \
        : "+f"((acc)[0]), "+f"((acc)[1]), "+f"((acc)[2]), "+f"((acc)[3])   \
        : "r"((a)[0]), "r"((a)[1]), "r"((a)[2]), "r"((a)[3]),              \
          "r"(b0), "r"(b1))

// ---------------------------------------------------------------------------
// k1: fold a: w1 = lin_w^T a1, c1 = lin_b.a1 (and 2)
// ---------------------------------------------------------------------------
__global__ void k1_prep(const float* __restrict__ lin_w,
                        const float* __restrict__ lin_b,
                        const float* __restrict__ a) {
    int f = threadIdx.x;
    __shared__ float sa1[E], sa2[E], red1[E], red2[E];
    float a1v = a[f], a2v = a[E + f];
    sa1[f] = a1v;
    sa2[f] = a2v;
    __syncthreads();
    float acc1 = 0.f, acc2 = 0.f;
#pragma unroll 8
    for (int e = 0; e < E; e++) {
        float lw = lin_w[e * F + f];
        acc1 += lw * sa1[e];
        acc2 += lw * sa2[e];
    }
    g_w1[f] = acc1;
    g_w2[f] = acc2;
    float lb = lin_b[f];
    red1[f] = lb * a1v;
    red2[f] = lb * a2v;
    __syncthreads();
    for (int s = 64; s > 0; s >>= 1) {
        if (f < s) {
            red1[f] += red1[f + s];
            red2[f] += red2[f + s];
        }
        __syncthreads();
    }
    if (f == 0) {
        g_c[0] = red1[0];
        g_c[1] = red2[0];
    }
}

// ---------------------------------------------------------------------------
// k2: s1/s2 row scores (exact fp32). One warp per row.
// ---------------------------------------------------------------------------
__global__ void k2_scores(const float* __restrict__ x) {
    int row = (blockIdx.x * blockDim.x + threadIdx.x) >> 5;
    int lane = threadIdx.x & 31;
    if (row >= B * K) return;
    float4 xv = ((const float4*)(x + (size_t)row * F))[lane];
    float4 w1 = ((const float4*)g_w1)[lane];
    float4 w2 = ((const float4*)g_w2)[lane];
    float d1 = xv.x * w1.x + xv.y * w1.y + xv.z * w1.z + xv.w * w1.w;
    float d2 = xv.x * w2.x + xv.y * w2.y + xv.z * w2.z + xv.w * w2.w;
#pragma unroll
    for (int off = 16; off; off >>= 1) {
        d1 += __shfl_xor_sync(~0u, d1, off);
        d2 += __shfl_xor_sync(~0u, d2, off);
    }
    if (lane == 0) {
        g_s1[row] = d1 + g_c[0];
        g_s2[row] = d2 + g_c[1];
    }
}

// ---------------------------------------------------------------------------
// k2h: fp32 -> fp16 conversion, 8 elems/thread.
// ---------------------------------------------------------------------------
__global__ void k2h_half(const float* __restrict__ src, __half* __restrict__ dst, int n8) {
    int i = blockIdx.x * 256 + threadIdx.x;
    if (i >= n8) return;
    float4 a = ((const float4*)src)[2 * i];
    float4 b = ((const float4*)src)[2 * i + 1];
    __half2 h[4];
    h[0] = __floats2half2_rn(a.x, a.y);
    h[1] = __floats2half2_rn(a.z, a.w);
    h[2] = __floats2half2_rn(b.x, b.y);
    h[3] = __floats2half2_rn(b.z, b.w);
    ((uint4*)dst)[i] = *(uint4*)h;
}

// ---------------------------------------------------------------------------
// k3g: GEMM with inline unnormalized softmax numerator.
// One block per (b, 128 i-rows), 8 warps as 2(m) x 4(n); warp tile 64 x 32.
// Single pass: per 64-j chunk compute E=exp(leaky(s1+s2)+bias) straight into
// the fp16 A-tile + row-sum registers; cp.async X tile; m16n8k16 MMA.
// Epilogue: h = acc*inv + x (fp16 store), writes g_inv for k3w.
// ---------------------------------------------------------------------------
__global__ void __launch_bounds__(256, 2) k3g(const float* __restrict__ x,
                                              const float* __restrict__ bias) {
    extern __shared__ char sm[];
    const uint32_t sbase = smem_u32(sm);
    float* s2s = (float*)(sm + OFF_S2);
    float* s1s = (float*)(sm + OFF_S1);
    float* invs = (float*)(sm + OFF_INV);

    const int tid = threadIdx.x;
    const int wid = tid >> 5, lane = tid & 31;
    const int b = blockIdx.y;
    const int i0 = blockIdx.x * 128;
    const int warp_m = (wid >> 2) * 64;  // 0 or 64
    const int warp_n = (wid & 3) * 32;   // 0..96
    const int qr = lane >> 2, qc = lane & 3;
    const int lrow = (lane & 7) | (((lane >> 3) & 1) << 3);
    const int lhi = (lane >> 4) * 8;

    const float* Xb = x + (size_t)b * K * F;
    const __half* Xh = g_xh + (size_t)b * K * F;

    const int prow = tid >> 1;        // 0..127 (A-tile / E row)
    const int pj0 = (tid & 1) * 32;   // j sub-range within chunk
    const int jx = tid >> 2, cx = tid & 3;  // X staging coords

    for (int j = tid; j < K; j += 256) s2s[j] = g_s2[b * K + j];
    if (tid < 128) s1s[tid] = g_s1[b * K + i0 + tid];
    __syncthreads();

    const float s1 = s1s[prow];
    float rsum = 0.f;

    float acc[4][4][4];
#pragma unroll
    for (int mt = 0; mt < 4; mt++)
#pragma unroll
        for (int nt = 0; nt < 4; nt++)
#pragma unroll
            for (int q = 0; q < 4; q++) acc[mt][nt][q] = 0.f;

#define STAGE_X(c, bi)                                                          \
    do {                                                                        \
        uint32_t xd = sbase + OFF_X + (bi) * XBUF;                              \
        _Pragma("unroll") for (int t = 0; t < 4; t++) {                         \
            int col = cx + t * 4;                                               \
            cp16(xd + jx * (XPH * 2) + col * 16,                                \
                 Xh + (size_t)((c) * CH + jx) * F + col * 8);                   \
        }                                                                       \
        cp_commit();                                                            \
    } while (0)

#define COMPUTE_E(c, bi)                                                            \
    do {                                                                            \
        const float* brow = bias + (size_t)(i0 + prow) * K + (c) * CH + pj0;        \
        const float* s2p = s2s + (c) * CH + pj0;                                    \
        __half2* ad = (__half2*)(sm + OFF_A + (bi) * ABUF + prow * (APH * 2) + pj0 * 2); \
        _Pragma("unroll") for (int q = 0; q < 8; q++) {                             \
            float4 bv = *(const float4*)(brow + q * 4);                             \
            float4 s2v = *(const float4*)(s2p + q * 4);                             \
            float v, e0, e1, e2, e3;                                                \
            v = s1 + s2v.x; v = (v > 0.f ? v : ALPHA * v) + bv.x; e0 = __expf(v);   \
            v = s1 + s2v.y; v = (v > 0.f ? v : ALPHA * v) + bv.y; e1 = __expf(v);   \
            v = s1 + s2v.z; v = (v > 0.f ? v : ALPHA * v) + bv.z; e2 = __expf(v);   \
            v = s1 + s2v.w; v = (v > 0.f ? v : ALPHA * v) + bv.w; e3 = __expf(v);   \
            rsum += (e0 + e1) + (e2 + e3);                                          \
            ad[q * 2] = __floats2half2_rn(e0, e1);                                  \
            ad[q * 2 + 1] = __floats2half2_rn(e2, e3);                              \
        }                                                                           \
    } while (0)

    STAGE_X(0, 0);
    COMPUTE_E(0, 0);
    for (int c = 0; c < NCH3; c++) {
        int bi = c & 1;
        if (c + 1 < NCH3) {
            STAGE_X(c + 1, bi ^ 1);
            COMPUTE_E(c + 1, bi ^ 1);
            CP_WAIT(1);
        } else {
            CP_WAIT(0);
        }
        __syncthreads();
        uint32_t pA = sbase + OFF_A + bi * ABUF + (warp_m + lrow) * (APH * 2) + lhi * 2;
        uint32_t pB = sbase + OFF_X + bi * XBUF + lrow * (XPH * 2) + (warp_n + lhi) * 2;
#pragma unroll
        for (int kk = 0; kk < 4; kk++) {
            uint32_t af[4][4];
#pragma unroll
            for (int mt = 0; mt < 4; mt++)
                ldsm4(af[mt], pA + mt * 16 * (APH * 2) + kk * 32);
            uint32_t bf[2][4];
            ldsm4t(bf[0], pB + kk * 16 * (XPH * 2));
            ldsm4t(bf[1], pB + kk * 16 * (XPH * 2) + 32);
#pragma unroll
            for (int mt = 0; mt < 4; mt++) {
                MMA_F16(acc[mt][0], af[mt], bf[0][0], bf[0][1]);
                MMA_F16(acc[mt][1], af[mt], bf[0][2], bf[0][3]);
                MMA_F16(acc[mt][2], af[mt], bf[1][0], bf[1][1]);
                MMA_F16(acc[mt][3], af[mt], bf[1][2], bf[1][3]);
            }
        }
        __syncthreads();
    }

    // row-sum: combine the 2 threads sharing a row (adjacent lanes)
    float total = rsum + __shfl_xor_sync(~0u, rsum, 1);
    if ((tid & 1) == 0) {
        float iv = 1.0f / total;
        invs[prow] = iv;
        g_inv[b * K + i0 + prow] = iv;
    }
    __syncthreads();

    // epilogue: h = acc*inv + x, fp16 store
#pragma unroll
    for (int mt = 0; mt < 4; mt++) {
        int lr = warp_m + mt * 16 + qr;
        float ivA = invs[lr];
        float ivB = invs[lr + 8];
        int r0 = i0 + lr;
#pragma unroll
        for (int nt = 0; nt < 4; nt++) {
            int fc = warp_n + nt * 8 + qc * 2;
            float2 xv0 = *(const float2*)(Xb + (size_t)r0 * F + fc);
            float2 xv1 = *(const float2*)(Xb + (size_t)(r0 + 8) * F + fc);
            *(__half2*)(g_hh + ((size_t)b * K + r0) * F + fc) =
                __floats2half2_rn(acc[mt][nt][0] * ivA + xv0.x, acc[mt][nt][1] * ivA + xv0.y);
            *(__half2*)(g_hh + ((size_t)b * K + r0 + 8) * F + fc) =
                __floats2half2_rn(acc[mt][nt][2] * ivB + xv1.x, acc[mt][nt][3] * ivB + xv1.y);
        }
    }
}

// ---------------------------------------------------------------------------
// k3w: stream attention = exp(leaky(s1+s2)+bias) * inv. Pure bandwidth.
// ---------------------------------------------------------------------------
__global__ void __launch_bounds__(256) k3w(const float* __restrict__ bias,
                                           float* __restrict__ attn) {
    __shared__ float s2s[K];
    int b = blockIdx.y;
    int tid = threadIdx.x, warp = tid >> 5, lane = tid & 31;
    for (int j = tid; j < K; j += 256) s2s[j] = g_s2[b * K + j];
    __syncthreads();
    int gi = blockIdx.x * 8 + warp;
    float s1 = g_s1[b * K + gi];
    float iv = g_inv[b * K + gi];
    const float4* brow = (const float4*)(bias + (size_t)gi * K);
    const float4* s2s4 = (const float4*)s2s;
    float4* arow = (float4*)(attn + ((size_t)(b * K + gi)) * K);
#pragma unroll
    for (int t = 0; t < 8; t++) {
        int j4 = lane + t * 32;
        float4 bv = brow[j4];
        float4 s2v = s2s4[j4];
        float v;
        float4 p;
        v = s1 + s2v.x; v = (v > 0.f ? v : ALPHA * v) + bv.x; p.x = __expf(v) * iv;
        v = s1 + s2v.y; v = (v > 0.f ? v : ALPHA * v) + bv.y; p.y = __expf(v) * iv;
        v = s1 + s2v.z; v = (v > 0.f ? v : ALPHA * v) + bv.z; p.z = __expf(v) * iv;
        v = s1 + s2v.w; v = (v > 0.f ? v : ALPHA * v) + bv.w; p.w = __expf(v) * iv;
        arow[j4] = p;
    }
}

// ---------------------------------------------------------------------------
// k4: h2 partial via fp16 mma. A = g_wh [o x k], B = g_hh [k x f].
// ---------------------------------------------------------------------------
__global__ void __launch_bounds__(256, 2) k4_lin2() {
    extern __shared__ char sm[];
    const uint32_t sbase = smem_u32(sm);
    const int tid = threadIdx.x;
    const int wid = tid >> 5, lane = tid & 31;
    const int b = blockIdx.x;
    const int ks = blockIdx.y;
    const int k0 = ks * (K / NSPLIT);
    const int warp_m = (wid >> 2) * 64;
    const int warp_n = (wid & 3) * 32;
    const int qr = lane >> 2, qc = lane & 3;

    const __half* Hb = g_hh + (size_t)b * K * F;
    const int rw = tid >> 1, cw = tid & 1;
    const int jx = tid >> 2, cx = tid & 3;
    const int lrow = (lane & 7) | (((lane >> 3) & 1) << 3);
    const int lhi = (lane >> 4) * 8;

    float acc[4][4][4];
#pragma unroll
    for (int mt = 0; mt < 4; mt++)
#pragma unroll
        for (int nt = 0; nt < 4; nt++)
#pragma unroll
            for (int q = 0; q < 4; q++) acc[mt][nt][q] = 0.f;

#define STAGE4(c, bi)                                                                 \
    do {                                                                              \
        uint32_t ad = sbase + (bi) * ABUF;                                            \
        uint32_t bd = sbase + 2 * ABUF + (bi) * XBUF;                                 \
        int vb = rw < OUT2 ? 16 : 0;                                                  \
        const __half* wsrc = g_wh + (size_t)(rw < OUT2 ? rw : 0) * K + k0 + (c) * CH; \
        _Pragma("unroll") for (int t = 0; t < 4; t++) {                               \
            int col = cw * 4 + t;                                                     \
            cp16z(ad + rw * (APH * 2) + col * 16, wsrc + col * 8, vb);                \
        }                                                                             \
        _Pragma("unroll") for (int t = 0; t < 4; t++) {                               \
            int col = cx + t * 4;                                                     \
            cp16(bd + jx * (XPH * 2) + col * 16,                                      \
                 Hb + (size_t)(k0 + (c) * CH + jx) * F + col * 8);                    \
        }                                                                             \
        cp_commit();                                                                  \
    } while (0)

    const int NCH4 = (K / NSPLIT) / CH;  // 4
    STAGE4(0, 0);
    for (int c = 0; c < NCH4; c++) {
        int bi = c & 1;
        if (c + 1 < NCH4) {
            STAGE4(c + 1, bi ^ 1);
            CP_WAIT(1);
        } else {
            CP_WAIT(0);
        }
        __syncthreads();
        uint32_t pA = sbase + bi * ABUF + (warp_m + lrow) * (APH * 2) + lhi * 2;
        uint32_t pB = sbase + 2 * ABUF + bi * XBUF + lrow * (XPH * 2) + (warp_n + lhi) * 2;
#pragma unroll
        for (int kk = 0; kk < 4; kk++) {
            uint32_t af[4][4];
#pragma unroll
            for (int mt = 0; mt < 4; mt++)
                ldsm4(af[mt], pA + mt * 16 * (APH * 2) + kk * 32);
            uint32_t bf[2][4];
#pragma unroll
            for (int ntp = 0; ntp < 2; ntp++)
                ldsm4t(bf[ntp], pB + kk * 16 * (XPH * 2) + ntp * 32);
#pragma unroll
            for (int mt = 0; mt < 4; mt++)
#pragma unroll
                for (int ntp = 0; ntp < 2; ntp++) {
                    MMA_F16(acc[mt][2 * ntp], af[mt], bf[ntp][0], bf[ntp][1]);
                    MMA_F16(acc[mt][2 * ntp + 1], af[mt], bf[ntp][2], bf[ntp][3]);
                }
        }
        __syncthreads();
    }

    float* out = g_h2p[ks] + (size_t)b * F * OUT2;
#pragma unroll
    for (int mt = 0; mt < 4; mt++) {
        int o0 = warp_m + mt * 16 + qr;
#pragma unroll
        for (int nt = 0; nt < 4; nt++) {
            int fc = warp_n + nt * 8 + qc * 2;
            if (o0 < OUT2) {
                out[(size_t)fc * OUT2 + o0] = acc[mt][nt][0];
                out[(size_t)(fc + 1) * OUT2 + o0] = acc[mt][nt][1];
            }
            if (o0 + 8 < OUT2) {
                out[(size_t)fc * OUT2 + o0 + 8] = acc[mt][nt][2];
                out[(size_t)(fc + 1) * OUT2 + o0 + 8] = acc[mt][nt][3];
            }
        }
    }
}

// ---------------------------------------------------------------------------
// k5: out = relu(sum partials + lin2_b)
// ---------------------------------------------------------------------------
__global__ void k5_out(const float* __restrict__ lin2_b, float* __restrict__ out) {
    int i = blockIdx.x * 256 + threadIdx.x;
    if (i >= B * F * OUT2) return;
    float v = lin2_b[i % OUT2];
#pragma unroll
    for (int p = 0; p < NSPLIT; p++) v += g_h2p[p][i];
    out[i] = v > 0.f ? v : 0.f;
}

// ---------------------------------------------------------------------------
extern "C" void kernel_launch(void* const* d_in, const int* in_sizes, int n_in,
                              void* d_out, int out_size) {
    const float* x      = (const float*)d_in[0];
    const float* lin_w  = (const float*)d_in[1];
    const float* lin_b  = (const float*)d_in[2];
    const float* a      = (const float*)d_in[3];
    const float* bias   = (const float*)d_in[4];
    const float* lin2_w = (const float*)d_in[5];
    const float* lin2_b = (const float*)d_in[6];
    float* out = (float*)d_out;
    float* out_h2 = out;                           // (B,F,OUT2)
    float* out_attn = out + (size_t)B * F * OUT2;  // (B,K,K)

    cudaFuncSetAttribute(k3g, cudaFuncAttributeMaxDynamicSharedMemorySize, SMEM_K3G);
    cudaFuncSetAttribute(k4_lin2, cudaFuncAttributeMaxDynamicSharedMemorySize, SMEM_K4);

    void* xh = nullptr;
    void* wh = nullptr;
    cudaGetSymbolAddress(&xh, g_xh);
    cudaGetSymbolAddress(&wh, g_wh);

    k1_prep<<<1, 128>>>(lin_w, lin_b, a);
    k2_scores<<<(B * K) / 8, 256>>>(x);
    k2h_half<<<(B * K * F / 8 + 255) / 256, 256>>>(x, (__half*)xh, B * K * F / 8);
    k2h_half<<<(OUT2 * K / 8 + 255) / 256, 256>>>(lin2_w, (__half*)wh, OUT2 * K / 8);
    k3g<<<dim3(K / 128, B), 256, SMEM_K3G>>>(x, bias);
    k3w<<<dim3(K / 8, B), 256>>>(bias, out_attn);
    k4_lin2<<<dim3(B, NSPLIT), 256, SMEM_K4>>>();
    k5_out<<<(B * F * OUT2 + 255) / 256, 256>>>(lin2_b, out_h2);
}

// round 10
// speedup vs baseline: 1.4728x; 1.0344x over previous
#include <cuda_runtime.h>
#include <cuda_fp16.h>
#include <cstdint>

#define B 32
#define K 1024
#define F 128
#define E 128
#define OUT2 125
#define ALPHA 0.2f

#define CH 64                 // j chunk width
#define NCH3 (K / CH)         // 16
#define APH 72                // A-tile pitch (halves), 144 B
#define ABUF (128 * APH * 2)  // 18432 B
#define XPH 136               // X/W/H-tile pitch (halves), 272 B
#define XBUF (CH * XPH * 2)   // 17408 B

// k3g smem offsets (bytes)
#define OFF_S2 0
#define OFF_S1 4096
#define OFF_INV 4608
#define OFF_A 5120                   // 2*ABUF = 36864 (also W tile: 34816)
#define OFF_X (OFF_A + 2 * ABUF)     // 41984: 2*XBUF = 34816 (also H tile)
#define SMEM_K3G (OFF_X + 2 * XBUF)  // 76800

// -------------------- scratch (device globals, allocation-free) ------------
__device__ float g_w1[F];
__device__ float g_w2[F];
__device__ float g_c[2];
__device__ float g_s1[B * K];
__device__ float g_s2[B * K];
__device__ float g_inv[B * K];
__device__ __half g_xh[(size_t)B * K * F];  // fp16 x
__device__ __half g_wh[128 * K];            // fp16 lin2_w (o rows 125..127 unused)
__device__ float g_h2[(size_t)B * F * OUT2];

__device__ __forceinline__ uint32_t smem_u32(const void* p) {
    uint32_t a;
    asm("{ .reg .u64 t; cvta.to.shared.u64 t, %1; cvt.u32.u64 %0, t; }" : "=r"(a) : "l"(p));
    return a;
}
__device__ __forceinline__ void cp16(uint32_t dst, const void* src) {
    asm volatile("cp.async.cg.shared.global [%0], [%1], 16;" :: "r"(dst), "l"(src) : "memory");
}
__device__ __forceinline__ void cp16z(uint32_t dst, const void* src, int bytes) {
    asm volatile("cp.async.cg.shared.global [%0], [%1], 16, %2;"
                 :: "r"(dst), "l"(src), "r"(bytes) : "memory");
}
__device__ __forceinline__ void cp_commit() {
    asm volatile("cp.async.commit_group;" ::: "memory");
}
#define CP_WAIT(n) asm volatile("cp.async.wait_group %0;" :: "n"(n) : "memory")

__device__ __forceinline__ void ldsm4(uint32_t* r, uint32_t addr) {
    asm volatile("ldmatrix.sync.aligned.m8n8.x4.shared.b16 {%0,%1,%2,%3}, [%4];"
                 : "=r"(r[0]), "=r"(r[1]), "=r"(r[2]), "=r"(r[3]) : "r"(addr));
}
__device__ __forceinline__ void ldsm4t(uint32_t* r, uint32_t addr) {
    asm volatile("ldmatrix.sync.aligned.m8n8.x4.trans.shared.b16 {%0,%1,%2,%3}, [%4];"
                 : "=r"(r[0]), "=r"(r[1]), "=r"(r[2]), "=r"(r[3]) : "r"(addr));
}
#define MMA_F16(acc, a, b0, b1)                                            \
    asm volatile(                                                          \
        "mma.sync.aligned.m16n8k16.row.col.f32.f16.f16.f32 "               \
        "{%0,%1,%2,%3}, {%4,%5,%6,%7}, {%8,%9}, {%0,%1,%2,%3};"            \
        : "+f"((acc)[0]), "+f"((acc)[1]), "+f"((acc)[2]), "+f"((acc)[3])   \
        : "r"((a)[0]), "r"((a)[1]), "r"((a)[2]), "r"((a)[3]),              \
          "r"(b0), "r"(b1))

// ---------------------------------------------------------------------------
// k1: fold a: w1 = lin_w^T a1, c1 = lin_b.a1 (and 2)
// ---------------------------------------------------------------------------
__global__ void k1_prep(const float* __restrict__ lin_w,
                        const float* __restrict__ lin_b,
                        const float* __restrict__ a) {
    int f = threadIdx.x;
    __shared__ float sa1[E], sa2[E], red1[E], red2[E];
    float a1v = a[f], a2v = a[E + f];
    sa1[f] = a1v;
    sa2[f] = a2v;
    __syncthreads();
    float acc1 = 0.f, acc2 = 0.f;
#pragma unroll 8
    for (int e = 0; e < E; e++) {
        float lw = lin_w[e * F + f];
        acc1 += lw * sa1[e];
        acc2 += lw * sa2[e];
    }
    g_w1[f] = acc1;
    g_w2[f] = acc2;
    float lb = lin_b[f];
    red1[f] = lb * a1v;
    red2[f] = lb * a2v;
    __syncthreads();
    for (int s = 64; s > 0; s >>= 1) {
        if (f < s) {
            red1[f] += red1[f + s];
            red2[f] += red2[f + s];
        }
        __syncthreads();
    }
    if (f == 0) {
        g_c[0] = red1[0];
        g_c[1] = red2[0];
    }
}

// ---------------------------------------------------------------------------
// k2: s1/s2 row scores (exact fp32) + fused x -> fp16. One warp per row.
// ---------------------------------------------------------------------------
__global__ void k2_scores(const float* __restrict__ x) {
    int row = (blockIdx.x * blockDim.x + threadIdx.x) >> 5;
    int lane = threadIdx.x & 31;
    if (row >= B * K) return;
    float4 xv = ((const float4*)(x + (size_t)row * F))[lane];
    // fused fp16 conversion (x is already in registers)
    __half2 hx0 = __floats2half2_rn(xv.x, xv.y);
    __half2 hx1 = __floats2half2_rn(xv.z, xv.w);
    uint2 pk;
    pk.x = *(uint32_t*)&hx0;
    pk.y = *(uint32_t*)&hx1;
    *(uint2*)(g_xh + (size_t)row * F + lane * 4) = pk;

    float4 w1 = ((const float4*)g_w1)[lane];
    float4 w2 = ((const float4*)g_w2)[lane];
    float d1 = xv.x * w1.x + xv.y * w1.y + xv.z * w1.z + xv.w * w1.w;
    float d2 = xv.x * w2.x + xv.y * w2.y + xv.z * w2.z + xv.w * w2.w;
#pragma unroll
    for (int off = 16; off; off >>= 1) {
        d1 += __shfl_xor_sync(~0u, d1, off);
        d2 += __shfl_xor_sync(~0u, d2, off);
    }
    if (lane == 0) {
        g_s1[row] = d1 + g_c[0];
        g_s2[row] = d2 + g_c[1];
    }
}

// ---------------------------------------------------------------------------
// k2h: fp32 -> fp16 conversion (lin2_w only now).
// ---------------------------------------------------------------------------
__global__ void k2h_half(const float* __restrict__ src, __half* __restrict__ dst, int n8) {
    int i = blockIdx.x * 256 + threadIdx.x;
    if (i >= n8) return;
    float4 a = ((const float4*)src)[2 * i];
    float4 b = ((const float4*)src)[2 * i + 1];
    __half2 h[4];
    h[0] = __floats2half2_rn(a.x, a.y);
    h[1] = __floats2half2_rn(a.z, a.w);
    h[2] = __floats2half2_rn(b.x, b.y);
    h[3] = __floats2half2_rn(b.z, b.w);
    ((uint4*)dst)[i] = *(uint4*)h;
}

// ---------------------------------------------------------------------------
// k3g: fused [softmax-numerator GEMM] + [lin2 GEMM].
// Phase 1 (per 64-j chunk): E=exp(leaky(s1+s2)+bias) -> fp16 A-tile + row
//   sums; cp.async X tile; mma -> acc = E @ x.
// Epilogue: h = acc*inv + x -> fp16 smem H-tile (no gmem h!).
// Phase 2: stage w k-slice [128o x 128k]; D[o][f] = w @ H; atomicAdd into
//   g_h2[b][f][o] (this block covers k in [i0, i0+128)).
// ---------------------------------------------------------------------------
__global__ void __launch_bounds__(256, 2) k3g(const float* __restrict__ x,
                                              const float* __restrict__ bias) {
    extern __shared__ char sm[];
    const uint32_t sbase = smem_u32(sm);
    float* s2s = (float*)(sm + OFF_S2);
    float* s1s = (float*)(sm + OFF_S1);
    float* invs = (float*)(sm + OFF_INV);

    const int tid = threadIdx.x;
    const int wid = tid >> 5, lane = tid & 31;
    const int b = blockIdx.y;
    const int i0 = blockIdx.x * 128;
    const int warp_m = (wid >> 2) * 64;  // 0 or 64
    const int warp_n = (wid & 3) * 32;   // 0..96
    const int qr = lane >> 2, qc = lane & 3;
    const int lrow = (lane & 7) | (((lane >> 3) & 1) << 3);
    const int lhi = (lane >> 4) * 8;

    const float* Xb = x + (size_t)b * K * F;
    const __half* Xh = g_xh + (size_t)b * K * F;

    const int prow = tid >> 1;
    const int pj0 = (tid & 1) * 32;
    const int jx = tid >> 2, cx = tid & 3;

    for (int j = tid; j < K; j += 256) s2s[j] = g_s2[b * K + j];
    if (tid < 128) s1s[tid] = g_s1[b * K + i0 + tid];
    __syncthreads();

    const float s1 = s1s[prow];
    float rsum = 0.f;

    float acc[4][4][4];
#pragma unroll
    for (int mt = 0; mt < 4; mt++)
#pragma unroll
        for (int nt = 0; nt < 4; nt++)
#pragma unroll
            for (int q = 0; q < 4; q++) acc[mt][nt][q] = 0.f;

#define STAGE_X(c, bi)                                                          \
    do {                                                                        \
        uint32_t xd = sbase + OFF_X + (bi) * XBUF;                              \
        _Pragma("unroll") for (int t = 0; t < 4; t++) {                         \
            int col = cx + t * 4;                                               \
            cp16(xd + jx * (XPH * 2) + col * 16,                                \
                 Xh + (size_t)((c) * CH + jx) * F + col * 8);                   \
        }                                                                       \
        cp_commit();                                                            \
    } while (0)

#define COMPUTE_E(c, bi)                                                            \
    do {                                                                            \
        const float* brow = bias + (size_t)(i0 + prow) * K + (c) * CH + pj0;        \
        const float* s2p = s2s + (c) * CH + pj0;                                    \
        __half2* ad = (__half2*)(sm + OFF_A + (bi) * ABUF + prow * (APH * 2) + pj0 * 2); \
        _Pragma("unroll") for (int q = 0; q < 8; q++) {                             \
            float4 bv = *(const float4*)(brow + q * 4);                             \
            float4 s2v = *(const float4*)(s2p + q * 4);                             \
            float v, e0, e1, e2, e3;                                                \
            v = s1 + s2v.x; v = (v > 0.f ? v : ALPHA * v) + bv.x; e0 = __expf(v);   \
            v = s1 + s2v.y; v = (v > 0.f ? v : ALPHA * v) + bv.y; e1 = __expf(v);   \
            v = s1 + s2v.z; v = (v > 0.f ? v : ALPHA * v) + bv.z; e2 = __expf(v);   \
            v = s1 + s2v.w; v = (v > 0.f ? v : ALPHA * v) + bv.w; e3 = __expf(v);   \
            rsum += (e0 + e1) + (e2 + e3);                                          \
            ad[q * 2] = __floats2half2_rn(e0, e1);                                  \
            ad[q * 2 + 1] = __floats2half2_rn(e2, e3);                              \
        }                                                                           \
    } while (0)

    STAGE_X(0, 0);
    COMPUTE_E(0, 0);
    for (int c = 0; c < NCH3; c++) {
        int bi = c & 1;
        if (c + 1 < NCH3) {
            STAGE_X(c + 1, bi ^ 1);
            COMPUTE_E(c + 1, bi ^ 1);
            CP_WAIT(1);
        } else {
            CP_WAIT(0);
        }
        __syncthreads();
        uint32_t pA = sbase + OFF_A + bi * ABUF + (warp_m + lrow) * (APH * 2) + lhi * 2;
        uint32_t pB = sbase + OFF_X + bi * XBUF + lrow * (XPH * 2) + (warp_n + lhi) * 2;
#pragma unroll
        for (int kk = 0; kk < 4; kk++) {
            uint32_t af[4][4];
#pragma unroll
            for (int mt = 0; mt < 4; mt++)
                ldsm4(af[mt], pA + mt * 16 * (APH * 2) + kk * 32);
            uint32_t bf[2][4];
            ldsm4t(bf[0], pB + kk * 16 * (XPH * 2));
            ldsm4t(bf[1], pB + kk * 16 * (XPH * 2) + 32);
#pragma unroll
            for (int mt = 0; mt < 4; mt++) {
                MMA_F16(acc[mt][0], af[mt], bf[0][0], bf[0][1]);
                MMA_F16(acc[mt][1], af[mt], bf[0][2], bf[0][3]);
                MMA_F16(acc[mt][2], af[mt], bf[1][0], bf[1][1]);
                MMA_F16(acc[mt][3], af[mt], bf[1][2], bf[1][3]);
            }
        }
        __syncthreads();
    }

    // ---- inv ----
    float total = rsum + __shfl_xor_sync(~0u, rsum, 1);
    if ((tid & 1) == 0) {
        float iv = 1.0f / total;
        invs[prow] = iv;
        g_inv[b * K + i0 + prow] = iv;
    }
    __syncthreads();

    // ---- epilogue: h = acc*inv + x -> fp16 H-tile in smem (OFF_X region) ----
#pragma unroll
    for (int mt = 0; mt < 4; mt++) {
        int lr = warp_m + mt * 16 + qr;
        float ivA = invs[lr];
        float ivB = invs[lr + 8];
        int r0 = i0 + lr;
#pragma unroll
        for (int nt = 0; nt < 4; nt++) {
            int fc = warp_n + nt * 8 + qc * 2;
            float2 xv0 = *(const float2*)(Xb + (size_t)r0 * F + fc);
            float2 xv1 = *(const float2*)(Xb + (size_t)(r0 + 8) * F + fc);
            *(__half2*)(sm + OFF_X + lr * (XPH * 2) + fc * 2) =
                __floats2half2_rn(acc[mt][nt][0] * ivA + xv0.x, acc[mt][nt][1] * ivA + xv0.y);
            *(__half2*)(sm + OFF_X + (lr + 8) * (XPH * 2) + fc * 2) =
                __floats2half2_rn(acc[mt][nt][2] * ivB + xv1.x, acc[mt][nt][3] * ivB + xv1.y);
        }
    }

    // ---- stage W k-slice [128 o x 128 k] into OFF_A (pitch XPH) ----
    {
        int wrow = tid >> 1;
        int wc0 = (tid & 1) * 8;
        int vb = wrow < OUT2 ? 16 : 0;
        const __half* wsrc = g_wh + (size_t)(wrow < OUT2 ? wrow : 0) * K + i0;
#pragma unroll
        for (int t = 0; t < 8; t++) {
            int col = wc0 + t;
            cp16z(sbase + OFF_A + wrow * (XPH * 2) + col * 16, wsrc + col * 8, vb);
        }
        cp_commit();
    }
    CP_WAIT(0);
    __syncthreads();

    // ---- phase 2: D[o][f] = W @ H  (M=128 o, N=128 f, K=128) ----
#pragma unroll
    for (int mt = 0; mt < 4; mt++)
#pragma unroll
        for (int nt = 0; nt < 4; nt++)
#pragma unroll
            for (int q = 0; q < 4; q++) acc[mt][nt][q] = 0.f;

    {
        uint32_t pW = sbase + OFF_A + (warp_m + lrow) * (XPH * 2) + lhi * 2;
        uint32_t pH = sbase + OFF_X + lrow * (XPH * 2) + (warp_n + lhi) * 2;
#pragma unroll
        for (int kk = 0; kk < 8; kk++) {
            uint32_t af[4][4];
#pragma unroll
            for (int mt = 0; mt < 4; mt++)
                ldsm4(af[mt], pW + mt * 16 * (XPH * 2) + kk * 32);
            uint32_t bf[2][4];
            ldsm4t(bf[0], pH + kk * 16 * (XPH * 2));
            ldsm4t(bf[1], pH + kk * 16 * (XPH * 2) + 32);
#pragma unroll
            for (int mt = 0; mt < 4; mt++) {
                MMA_F16(acc[mt][0], af[mt], bf[0][0], bf[0][1]);
                MMA_F16(acc[mt][1], af[mt], bf[0][2], bf[0][3]);
                MMA_F16(acc[mt][2], af[mt], bf[1][0], bf[1][1]);
                MMA_F16(acc[mt][3], af[mt], bf[1][2], bf[1][3]);
            }
        }
    }

    // ---- atomic accumulate into g_h2[b][f][o] ----
    float* h2b = g_h2 + (size_t)b * F * OUT2;
#pragma unroll
    for (int mt = 0; mt < 4; mt++) {
        int o0 = warp_m + mt * 16 + qr;
#pragma unroll
        for (int nt = 0; nt < 4; nt++) {
            int fc = warp_n + nt * 8 + qc * 2;
            if (o0 < OUT2) {
                atomicAdd(&h2b[(size_t)fc * OUT2 + o0], acc[mt][nt][0]);
                atomicAdd(&h2b[(size_t)(fc + 1) * OUT2 + o0], acc[mt][nt][1]);
            }
            if (o0 + 8 < OUT2) {
                atomicAdd(&h2b[(size_t)fc * OUT2 + o0 + 8], acc[mt][nt][2]);
                atomicAdd(&h2b[(size_t)(fc + 1) * OUT2 + o0 + 8], acc[mt][nt][3]);
            }
        }
    }
}

// ---------------------------------------------------------------------------
// k3w: stream attention = exp(leaky(s1+s2)+bias) * inv. Pure bandwidth.
// ---------------------------------------------------------------------------
__global__ void __launch_bounds__(256) k3w(const float* __restrict__ bias,
                                           float* __restrict__ attn) {
    __shared__ float s2s[K];
    int b = blockIdx.y;
    int tid = threadIdx.x, warp = tid >> 5, lane = tid & 31;
    for (int j = tid; j < K; j += 256) s2s[j] = g_s2[b * K + j];
    __syncthreads();
    int gi = blockIdx.x * 8 + warp;
    float s1 = g_s1[b * K + gi];
    float iv = g_inv[b * K + gi];
    const float4* brow = (const float4*)(bias + (size_t)gi * K);
    const float4* s2s4 = (const float4*)s2s;
    float4* arow = (float4*)(attn + ((size_t)(b * K + gi)) * K);
#pragma unroll
    for (int t = 0; t < 8; t++) {
        int j4 = lane + t * 32;
        float4 bv = brow[j4];
        float4 s2v = s2s4[j4];
        float v;
        float4 p;
        v = s1 + s2v.x; v = (v > 0.f ? v : ALPHA * v) + bv.x; p.x = __expf(v) * iv;
        v = s1 + s2v.y; v = (v > 0.f ? v : ALPHA * v) + bv.y; p.y = __expf(v) * iv;
        v = s1 + s2v.z; v = (v > 0.f ? v : ALPHA * v) + bv.z; p.z = __expf(v) * iv;
        v = s1 + s2v.w; v = (v > 0.f ? v : ALPHA * v) + bv.w; p.w = __expf(v) * iv;
        arow[j4] = p;
    }
}

// ---------------------------------------------------------------------------
// k5: out = relu(g_h2 + lin2_b)
// ---------------------------------------------------------------------------
__global__ void k5_out(const float* __restrict__ lin2_b, float* __restrict__ out) {
    int i = blockIdx.x * 256 + threadIdx.x;
    if (i >= B * F * OUT2) return;
    float v = g_h2[i] + lin2_b[i % OUT2];
    out[i] = v > 0.f ? v : 0.f;
}

// ---------------------------------------------------------------------------
extern "C" void kernel_launch(void* const* d_in, const int* in_sizes, int n_in,
                              void* d_out, int out_size) {
    const float* x      = (const float*)d_in[0];
    const float* lin_w  = (const float*)d_in[1];
    const float* lin_b  = (const float*)d_in[2];
    const float* a      = (const float*)d_in[3];
    const float* bias   = (const float*)d_in[4];
    const float* lin2_w = (const float*)d_in[5];
    const float* lin2_b = (const float*)d_in[6];
    float* out = (float*)d_out;
    float* out_h2 = out;                           // (B,F,OUT2)
    float* out_attn = out + (size_t)B * F * OUT2;  // (B,K,K)

    cudaFuncSetAttribute(k3g, cudaFuncAttributeMaxDynamicSharedMemorySize, SMEM_K3G);

    void* wh = nullptr;
    void* h2 = nullptr;
    cudaGetSymbolAddress(&wh, g_wh);
    cudaGetSymbolAddress(&h2, g_h2);

    cudaMemsetAsync(h2, 0, sizeof(float) * B * F * OUT2);
    k1_prep<<<1, 128>>>(lin_w, lin_b, a);
    k2_scores<<<(B * K) / 8, 256>>>(x);
    k2h_half<<<(OUT2 * K / 8 + 255) / 256, 256>>>(lin2_w, (__half*)wh, OUT2 * K / 8);
    k3g<<<dim3(K / 128, B), 256, SMEM_K3G>>>(x, bias);
    k3w<<<dim3(K / 8, B), 256>>>(bias, out_attn);
    k5_out<<<(B * F * OUT2 + 255) / 256, 256>>>(lin2_b, out_h2);
}

// round 11
// speedup vs baseline: 1.5180x; 1.0307x over previous
#include <cuda_runtime.h>
#include <cuda_fp16.h>
#include <cstdint>

#define B 32
#define K 1024
#define F 128
#define E 128
#define OUT2 125
#define ALPHA 0.2f

#define CH 64          // j chunk width
#define NCH3 (K / CH)  // 16
#define ABUF 16384     // A-tile: 128 rows x 128 B (swizzled, no padding)
#define XBUF 16384     // X-tile: 64 rows x 256 B (swizzled)

// k3g smem offsets (bytes)
#define OFF_S2 0
#define OFF_S1 4096
#define OFF_INV 4608
#define OFF_A 5120                   // 2*ABUF (also W tile 128x256 in phase 2)
#define OFF_X (OFF_A + 2 * ABUF)     // 37888; 2*XBUF (also H tile 128x256)
#define SMEM_K3G (OFF_X + 2 * XBUF)  // 70656

// -------------------- scratch (device globals, allocation-free) ------------
__device__ float g_w1[F];
__device__ float g_w2[F];
__device__ float g_c[2];
__device__ float g_s1[B * K];
__device__ float g_s2[B * K];
__device__ float g_inv[B * K];
__device__ __half g_xh[(size_t)B * K * F];  // fp16 x
__device__ __half g_wh[128 * K];            // fp16 lin2_w (rows 125..127 unused)
__device__ float g_h2[(size_t)B * F * OUT2];

__device__ __forceinline__ uint32_t smem_u32(const void* p) {
    uint32_t a;
    asm("{ .reg .u64 t; cvta.to.shared.u64 t, %1; cvt.u32.u64 %0, t; }" : "=r"(a) : "l"(p));
    return a;
}
// swizzled addressing: 16B-column c16 XORed with row&7
__device__ __forceinline__ uint32_t swzA(int row, int c16) {  // pitch 128 B, c16 0..7
    return row * 128 + (((c16 ^ row) & 7) << 4);
}
__device__ __forceinline__ uint32_t swzX(int row, int c16) {  // pitch 256 B, c16 0..15
    return row * 256 + ((((c16) & 8) | ((c16 ^ row) & 7)) << 4);
}
__device__ __forceinline__ void cp16(uint32_t dst, const void* src) {
    asm volatile("cp.async.cg.shared.global [%0], [%1], 16;" :: "r"(dst), "l"(src) : "memory");
}
__device__ __forceinline__ void cp16z(uint32_t dst, const void* src, int bytes) {
    asm volatile("cp.async.cg.shared.global [%0], [%1], 16, %2;"
                 :: "r"(dst), "l"(src), "r"(bytes) : "memory");
}
__device__ __forceinline__ void cp_commit() {
    asm volatile("cp.async.commit_group;" ::: "memory");
}
#define CP_WAIT(n) asm volatile("cp.async.wait_group %0;" :: "n"(n) : "memory")

__device__ __forceinline__ void ldsm4(uint32_t* r, uint32_t addr) {
    asm volatile("ldmatrix.sync.aligned.m8n8.x4.shared.b16 {%0,%1,%2,%3}, [%4];"
                 : "=r"(r[0]), "=r"(r[1]), "=r"(r[2]), "=r"(r[3]) : "r"(addr));
}
__device__ __forceinline__ void ldsm4t(uint32_t* r, uint32_t addr) {
    asm volatile("ldmatrix.sync.aligned.m8n8.x4.trans.shared.b16 {%0,%1,%2,%3}, [%4];"
                 : "=r"(r[0]), "=r"(r[1]), "=r"(r[2]), "=r"(r[3]) : "r"(addr));
}
#define MMA_F16(acc, a, b0, b1)                                            \
    asm volatile(                                                          \
        "mma.sync.aligned.m16n8k16.row.col.f32.f16.f16.f32 "               \
        "{%0,%1,%2,%3}, {%4,%5,%6,%7}, {%8,%9}, {%0,%1,%2,%3};"            \
        : "+f"((acc)[0]), "+f"((acc)[1]), "+f"((acc)[2]), "+f"((acc)[3])   \
        : "r"((a)[0]), "r"((a)[1]), "r"((a)[2]), "r"((a)[3]),              \
          "r"(b0), "r"(b1))

// ---------------------------------------------------------------------------
// k1: fold a: w1 = lin_w^T a1, c1 = lin_b.a1 (and 2)
// ---------------------------------------------------------------------------
__global__ void k1_prep(const float* __restrict__ lin_w,
                        const float* __restrict__ lin_b,
                        const float* __restrict__ a) {
    int f = threadIdx.x;
    __shared__ float sa1[E], sa2[E], red1[E], red2[E];
    float a1v = a[f], a2v = a[E + f];
    sa1[f] = a1v;
    sa2[f] = a2v;
    __syncthreads();
    float acc1 = 0.f, acc2 = 0.f;
#pragma unroll 8
    for (int e = 0; e < E; e++) {
        float lw = lin_w[e * F + f];
        acc1 += lw * sa1[e];
        acc2 += lw * sa2[e];
    }
    g_w1[f] = acc1;
    g_w2[f] = acc2;
    float lb = lin_b[f];
    red1[f] = lb * a1v;
    red2[f] = lb * a2v;
    __syncthreads();
    for (int s = 64; s > 0; s >>= 1) {
        if (f < s) {
            red1[f] += red1[f + s];
            red2[f] += red2[f + s];
        }
        __syncthreads();
    }
    if (f == 0) {
        g_c[0] = red1[0];
        g_c[1] = red2[0];
    }
}

// ---------------------------------------------------------------------------
// k2: s1/s2 row scores (exact fp32) + fused x -> fp16. One warp per row.
// ---------------------------------------------------------------------------
__global__ void k2_scores(const float* __restrict__ x) {
    int row = (blockIdx.x * blockDim.x + threadIdx.x) >> 5;
    int lane = threadIdx.x & 31;
    if (row >= B * K) return;
    float4 xv = ((const float4*)(x + (size_t)row * F))[lane];
    __half2 hx0 = __floats2half2_rn(xv.x, xv.y);
    __half2 hx1 = __floats2half2_rn(xv.z, xv.w);
    uint2 pk;
    pk.x = *(uint32_t*)&hx0;
    pk.y = *(uint32_t*)&hx1;
    *(uint2*)(g_xh + (size_t)row * F + lane * 4) = pk;

    float4 w1 = ((const float4*)g_w1)[lane];
    float4 w2 = ((const float4*)g_w2)[lane];
    float d1 = xv.x * w1.x + xv.y * w1.y + xv.z * w1.z + xv.w * w1.w;
    float d2 = xv.x * w2.x + xv.y * w2.y + xv.z * w2.z + xv.w * w2.w;
#pragma unroll
    for (int off = 16; off; off >>= 1) {
        d1 += __shfl_xor_sync(~0u, d1, off);
        d2 += __shfl_xor_sync(~0u, d2, off);
    }
    if (lane == 0) {
        g_s1[row] = d1 + g_c[0];
        g_s2[row] = d2 + g_c[1];
    }
}

// ---------------------------------------------------------------------------
// k2h: fp32 -> fp16 conversion (lin2_w only).
// ---------------------------------------------------------------------------
__global__ void k2h_half(const float* __restrict__ src, __half* __restrict__ dst, int n8) {
    int i = blockIdx.x * 256 + threadIdx.x;
    if (i >= n8) return;
    float4 a = ((const float4*)src)[2 * i];
    float4 b = ((const float4*)src)[2 * i + 1];
    __half2 h[4];
    h[0] = __floats2half2_rn(a.x, a.y);
    h[1] = __floats2half2_rn(a.z, a.w);
    h[2] = __floats2half2_rn(b.x, b.y);
    h[3] = __floats2half2_rn(b.z, b.w);
    ((uint4*)dst)[i] = *(uint4*)h;
}

// ---------------------------------------------------------------------------
// k3g: fused [softmax-numerator GEMM] + [lin2 GEMM], swizzled smem.
// ---------------------------------------------------------------------------
__global__ void __launch_bounds__(256, 2) k3g(const float* __restrict__ x,
                                              const float* __restrict__ bias) {
    extern __shared__ char sm[];
    const uint32_t sbase = smem_u32(sm);
    float* s2s = (float*)(sm + OFF_S2);
    float* s1s = (float*)(sm + OFF_S1);
    float* invs = (float*)(sm + OFF_INV);

    const int tid = threadIdx.x;
    const int wid = tid >> 5, lane = tid & 31;
    const int b = blockIdx.y;
    const int i0 = blockIdx.x * 128;
    const int warp_m = (wid >> 2) * 64;  // 0 or 64
    const int warp_n = (wid & 3) * 32;   // 0..96
    const int wn8 = warp_n >> 3;
    const int qr = lane >> 2, qc = lane & 3;
    const int lrow = (lane & 7) | (((lane >> 3) & 1) << 3);
    const int hi = lane >> 4;  // 0 or 1
    const int r7 = lane & 7;

    const float* Xb = x + (size_t)b * K * F;
    const __half* Xh = g_xh + (size_t)b * K * F;

    const int prow = tid >> 1;           // 0..127 (E row)
    const int pj0 = (tid & 1) * 32;      // half-col base within chunk
    const int pc16 = (tid & 1) * 4;      // 16B-col base
    const int jx = tid >> 2, cx = tid & 3;  // X staging coords

    for (int j = tid; j < K; j += 256) s2s[j] = g_s2[b * K + j];
    if (tid < 128) s1s[tid] = g_s1[b * K + i0 + tid];
    __syncthreads();

    const float s1 = s1s[prow];
    float rsum = 0.f;

    float acc[4][4][4];
#pragma unroll
    for (int mt = 0; mt < 4; mt++)
#pragma unroll
        for (int nt = 0; nt < 4; nt++)
#pragma unroll
            for (int q = 0; q < 4; q++) acc[mt][nt][q] = 0.f;

#define STAGE_X(c, bi)                                                          \
    do {                                                                        \
        uint32_t xd = sbase + OFF_X + (bi) * XBUF;                              \
        _Pragma("unroll") for (int t = 0; t < 4; t++) {                         \
            int c16 = cx * 4 + t;                                               \
            cp16(xd + swzX(jx, c16),                                            \
                 Xh + (size_t)((c) * CH + jx) * F + c16 * 8);                   \
        }                                                                       \
        cp_commit();                                                            \
    } while (0)

#define COMPUTE_E(c, bi)                                                             \
    do {                                                                             \
        const float* brow = bias + (size_t)(i0 + prow) * K + (c) * CH + pj0;         \
        const float* s2p = s2s + (c) * CH + pj0;                                     \
        char* abase = sm + OFF_A + (bi) * ABUF;                                      \
        _Pragma("unroll") for (int t = 0; t < 4; t++) {                              \
            uint32_t hb[4];                                                          \
            _Pragma("unroll") for (int qq = 0; qq < 2; qq++) {                       \
                int q = t * 2 + qq;                                                  \
                float4 bv = *(const float4*)(brow + q * 4);                          \
                float4 s2v = *(const float4*)(s2p + q * 4);                          \
                float v, e0, e1, e2, e3;                                             \
                v = s1 + s2v.x; v = (v > 0.f ? v : ALPHA * v) + bv.x; e0 = __expf(v); \
                v = s1 + s2v.y; v = (v > 0.f ? v : ALPHA * v) + bv.y; e1 = __expf(v); \
                v = s1 + s2v.z; v = (v > 0.f ? v : ALPHA * v) + bv.z; e2 = __expf(v); \
                v = s1 + s2v.w; v = (v > 0.f ? v : ALPHA * v) + bv.w; e3 = __expf(v); \
                rsum += (e0 + e1) + (e2 + e3);                                       \
                __half2 p0 = __floats2half2_rn(e0, e1);                              \
                __half2 p1 = __floats2half2_rn(e2, e3);                              \
                hb[qq * 2] = *(uint32_t*)&p0;                                        \
                hb[qq * 2 + 1] = *(uint32_t*)&p1;                                    \
            }                                                                        \
            *(uint4*)(abase + swzA(prow, pc16 + t)) = *(uint4*)hb;                   \
        }                                                                            \
    } while (0)

    STAGE_X(0, 0);
    COMPUTE_E(0, 0);
    for (int c = 0; c < NCH3; c++) {
        int bi = c & 1;
        if (c + 1 < NCH3) {
            STAGE_X(c + 1, bi ^ 1);
            COMPUTE_E(c + 1, bi ^ 1);
            CP_WAIT(1);
        } else {
            CP_WAIT(0);
        }
        __syncthreads();
        uint32_t aA = sbase + OFF_A + bi * ABUF;
        uint32_t aX = sbase + OFF_X + bi * XBUF;
#pragma unroll
        for (int kk = 0; kk < 4; kk++) {
            int sA = ((kk * 2 + hi) ^ r7) & 7;  // swizzled c16 for A
            uint32_t af[4][4];
#pragma unroll
            for (int mt = 0; mt < 4; mt++)
                ldsm4(af[mt], aA + (warp_m + mt * 16 + lrow) * 128 + (sA << 4));
            uint32_t bf[2][4];
#pragma unroll
            for (int ntp = 0; ntp < 2; ntp++) {
                int c16 = wn8 + 2 * ntp + hi;
                ldsm4t(bf[ntp], aX + swzX(kk * 16 + lrow, c16));
            }
#pragma unroll
            for (int mt = 0; mt < 4; mt++) {
                MMA_F16(acc[mt][0], af[mt], bf[0][0], bf[0][1]);
                MMA_F16(acc[mt][1], af[mt], bf[0][2], bf[0][3]);
                MMA_F16(acc[mt][2], af[mt], bf[1][0], bf[1][1]);
                MMA_F16(acc[mt][3], af[mt], bf[1][2], bf[1][3]);
            }
        }
        __syncthreads();
    }

    // ---- inv ----
    float total = rsum + __shfl_xor_sync(~0u, rsum, 1);
    if ((tid & 1) == 0) {
        float iv = 1.0f / total;
        invs[prow] = iv;
        g_inv[b * K + i0 + prow] = iv;
    }
    __syncthreads();

    // ---- epilogue: h = acc*inv + x -> fp16 H-tile (OFF_X, pitch 256 swz) ----
#pragma unroll
    for (int mt = 0; mt < 4; mt++) {
        int lr = warp_m + mt * 16 + qr;
        float ivA = invs[lr];
        float ivB = invs[lr + 8];
        int r0 = i0 + lr;
#pragma unroll
        for (int nt = 0; nt < 4; nt++) {
            int fc = warp_n + nt * 8 + qc * 2;
            int c16 = wn8 + nt;
            float2 xv0 = *(const float2*)(Xb + (size_t)r0 * F + fc);
            float2 xv1 = *(const float2*)(Xb + (size_t)(r0 + 8) * F + fc);
            *(__half2*)(sm + OFF_X + swzX(lr, c16) + 4 * qc) =
                __floats2half2_rn(acc[mt][nt][0] * ivA + xv0.x, acc[mt][nt][1] * ivA + xv0.y);
            *(__half2*)(sm + OFF_X + swzX(lr + 8, c16) + 4 * qc) =
                __floats2half2_rn(acc[mt][nt][2] * ivB + xv1.x, acc[mt][nt][3] * ivB + xv1.y);
        }
    }

    // ---- stage W k-slice [128 o x 128 k] into OFF_A (pitch 256 swz) ----
    {
        int wrow = tid >> 1;
        int wc0 = (tid & 1) * 8;
        int vb = wrow < OUT2 ? 16 : 0;
        const __half* wsrc = g_wh + (size_t)(wrow < OUT2 ? wrow : 0) * K + i0;
#pragma unroll
        for (int t = 0; t < 8; t++) {
            int c16 = wc0 + t;
            cp16z(sbase + OFF_A + swzX(wrow, c16), wsrc + c16 * 8, vb);
        }
        cp_commit();
    }
    CP_WAIT(0);
    __syncthreads();

    // ---- phase 2: D[o][f] = W @ H  (M=128 o, N=128 f, K=128) ----
#pragma unroll
    for (int mt = 0; mt < 4; mt++)
#pragma unroll
        for (int nt = 0; nt < 4; nt++)
#pragma unroll
            for (int q = 0; q < 4; q++) acc[mt][nt][q] = 0.f;

#pragma unroll
    for (int kk = 0; kk < 8; kk++) {
        uint32_t af[4][4];
#pragma unroll
        for (int mt = 0; mt < 4; mt++)
            ldsm4(af[mt], sbase + OFF_A + swzX(warp_m + mt * 16 + lrow, kk * 2 + hi));
        uint32_t bf[2][4];
#pragma unroll
        for (int ntp = 0; ntp < 2; ntp++)
            ldsm4t(bf[ntp], sbase + OFF_X + swzX(kk * 16 + lrow, wn8 + 2 * ntp + hi));
#pragma unroll
        for (int mt = 0; mt < 4; mt++) {
            MMA_F16(acc[mt][0], af[mt], bf[0][0], bf[0][1]);
            MMA_F16(acc[mt][1], af[mt], bf[0][2], bf[0][3]);
            MMA_F16(acc[mt][2], af[mt], bf[1][0], bf[1][1]);
            MMA_F16(acc[mt][3], af[mt], bf[1][2], bf[1][3]);
        }
    }

    // ---- atomic accumulate into g_h2[b][f][o] ----
    float* h2b = g_h2 + (size_t)b * F * OUT2;
#pragma unroll
    for (int mt = 0; mt < 4; mt++) {
        int o0 = warp_m + mt * 16 + qr;
#pragma unroll
        for (int nt = 0; nt < 4; nt++) {
            int fc = warp_n + nt * 8 + qc * 2;
            if (o0 < OUT2) {
                atomicAdd(&h2b[(size_t)fc * OUT2 + o0], acc[mt][nt][0]);
                atomicAdd(&h2b[(size_t)(fc + 1) * OUT2 + o0], acc[mt][nt][1]);
            }
            if (o0 + 8 < OUT2) {
                atomicAdd(&h2b[(size_t)fc * OUT2 + o0 + 8], acc[mt][nt][2]);
                atomicAdd(&h2b[(size_t)(fc + 1) * OUT2 + o0 + 8], acc[mt][nt][3]);
            }
        }
    }
}

// ---------------------------------------------------------------------------
// k3w: stream attention = exp(leaky(s1+s2)+bias) * inv. Pure bandwidth.
// ---------------------------------------------------------------------------
__global__ void __launch_bounds__(256) k3w(const float* __restrict__ bias,
                                           float* __restrict__ attn) {
    __shared__ float s2s[K];
    int b = blockIdx.y;
    int tid = threadIdx.x, warp = tid >> 5, lane = tid & 31;
    for (int j = tid; j < K; j += 256) s2s[j] = g_s2[b * K + j];
    __syncthreads();
    int gi = blockIdx.x * 8 + warp;
    float s1 = g_s1[b * K + gi];
    float iv = g_inv[b * K + gi];
    const float4* brow = (const float4*)(bias + (size_t)gi * K);
    const float4* s2s4 = (const float4*)s2s;
    float4* arow = (float4*)(attn + ((size_t)(b * K + gi)) * K);
#pragma unroll
    for (int t = 0; t < 8; t++) {
        int j4 = lane + t * 32;
        float4 bv = brow[j4];
        float4 s2v = s2s4[j4];
        float v;
        float4 p;
        v = s1 + s2v.x; v = (v > 0.f ? v : ALPHA * v) + bv.x; p.x = __expf(v) * iv;
        v = s1 + s2v.y; v = (v > 0.f ? v : ALPHA * v) + bv.y; p.y = __expf(v) * iv;
        v = s1 + s2v.z; v = (v > 0.f ? v : ALPHA * v) + bv.z; p.z = __expf(v) * iv;
        v = s1 + s2v.w; v = (v > 0.f ? v : ALPHA * v) + bv.w; p.w = __expf(v) * iv;
        arow[j4] = p;
    }
}

// ---------------------------------------------------------------------------
// k5: out = relu(g_h2 + lin2_b)
// ---------------------------------------------------------------------------
__global__ void k5_out(const float* __restrict__ lin2_b, float* __restrict__ out) {
    int i = blockIdx.x * 256 + threadIdx.x;
    if (i >= B * F * OUT2) return;
    float v = g_h2[i] + lin2_b[i % OUT2];
    out[i] = v > 0.f ? v : 0.f;
}

// ---------------------------------------------------------------------------
extern "C" void kernel_launch(void* const* d_in, const int* in_sizes, int n_in,
                              void* d_out, int out_size) {
    const float* x      = (const float*)d_in[0];
    const float* lin_w  = (const float*)d_in[1];
    const float* lin_b  = (const float*)d_in[2];
    const float* a      = (const float*)d_in[3];
    const float* bias   = (const float*)d_in[4];
    const float* lin2_w = (const float*)d_in[5];
    const float* lin2_b = (const float*)d_in[6];
    float* out = (float*)d_out;
    float* out_h2 = out;                           // (B,F,OUT2)
    float* out_attn = out + (size_t)B * F * OUT2;  // (B,K,K)

    cudaFuncSetAttribute(k3g, cudaFuncAttributeMaxDynamicSharedMemorySize, SMEM_K3G);

    void* wh = nullptr;
    void* h2 = nullptr;
    cudaGetSymbolAddress(&wh, g_wh);
    cudaGetSymbolAddress(&h2, g_h2);

    cudaMemsetAsync(h2, 0, sizeof(float) * B * F * OUT2);
    k1_prep<<<1, 128>>>(lin_w, lin_b, a);
    k2_scores<<<(B * K) / 8, 256>>>(x);
    k2h_half<<<(OUT2 * K / 8 + 255) / 256, 256>>>(lin2_w, (__half*)wh, OUT2 * K / 8);
    k3g<<<dim3(K / 128, B), 256, SMEM_K3G>>>(x, bias);
    k3w<<<dim3(K / 8, B), 256>>>(bias, out_attn);
    k5_out<<<(B * F * OUT2 + 255) / 256, 256>>>(lin2_b, out_h2);
}

// round 12
// speedup vs baseline: 1.6194x; 1.0668x over previous
#include <cuda_runtime.h>
#include <cuda_fp16.h>
#include <cstdint>

#define B 32
#define K 1024
#define F 128
#define E 128
#define OUT2 125
#define ALPHA 0.2f

#define CH 64          // j chunk width
#define NCH3 (K / CH)  // 16
#define ABUF 16384     // A-tile: 128 rows x 128 B (swizzled)
#define XBUF 16384     // X-tile: 64 rows x 256 B (swizzled)

// k3g smem offsets (bytes)
#define OFF_S2 0
#define OFF_S1 4096
#define OFF_INV 4608
#define OFF_A 5120                   // 2*ABUF (also W tile 128x256 in phase 2)
#define OFF_X (OFF_A + 2 * ABUF)     // 37888; 2*XBUF (also H tile 128x256)
#define SMEM_K3G (OFF_X + 2 * XBUF)  // 70656

// -------------------- scratch (device globals, allocation-free) ------------
__device__ float g_w1[F];
__device__ float g_w2[F];
__device__ float g_c[2];
__device__ float g_s1[B * K];
__device__ float g_s2[B * K];
__device__ float g_inv[B * K];
__device__ __half g_xh[(size_t)B * K * F];  // fp16 x
__device__ __half g_wh[128 * K];            // fp16 lin2_w (rows 125..127 unused)
__device__ float g_h2[(size_t)B * F * OUT2];

__device__ __forceinline__ uint32_t smem_u32(const void* p) {
    uint32_t a;
    asm("{ .reg .u64 t; cvta.to.shared.u64 t, %1; cvt.u32.u64 %0, t; }" : "=r"(a) : "l"(p));
    return a;
}
__device__ __forceinline__ uint32_t swzA(int row, int c16) {  // pitch 128 B
    return row * 128 + (((c16 ^ row) & 7) << 4);
}
__device__ __forceinline__ uint32_t swzX(int row, int c16) {  // pitch 256 B
    return row * 256 + ((((c16) & 8) | ((c16 ^ row) & 7)) << 4);
}
__device__ __forceinline__ void cp16(uint32_t dst, const void* src) {
    asm volatile("cp.async.cg.shared.global [%0], [%1], 16;" :: "r"(dst), "l"(src) : "memory");
}
__device__ __forceinline__ void cp16z(uint32_t dst, const void* src, int bytes) {
    asm volatile("cp.async.cg.shared.global [%0], [%1], 16, %2;"
                 :: "r"(dst), "l"(src), "r"(bytes) : "memory");
}
__device__ __forceinline__ void cp_commit() {
    asm volatile("cp.async.commit_group;" ::: "memory");
}
#define CP_WAIT(n) asm volatile("cp.async.wait_group %0;" :: "n"(n) : "memory")

__device__ __forceinline__ void ldsm4(uint32_t* r, uint32_t addr) {
    asm volatile("ldmatrix.sync.aligned.m8n8.x4.shared.b16 {%0,%1,%2,%3}, [%4];"
                 : "=r"(r[0]), "=r"(r[1]), "=r"(r[2]), "=r"(r[3]) : "r"(addr));
}
__device__ __forceinline__ void ldsm4t(uint32_t* r, uint32_t addr) {
    asm volatile("ldmatrix.sync.aligned.m8n8.x4.trans.shared.b16 {%0,%1,%2,%3}, [%4];"
                 : "=r"(r[0]), "=r"(r[1]), "=r"(r[2]), "=r"(r[3]) : "r"(addr));
}
#define MMA_F16(acc, a, b0, b1)                                            \
    asm volatile(                                                          \
        "mma.sync.aligned.m16n8k16.row.col.f32.f16.f16.f32 "               \
        "{%0,%1,%2,%3}, {%4,%5,%6,%7}, {%8,%9}, {%0,%1,%2,%3};"            \
        : "+f"((acc)[0]), "+f"((acc)[1]), "+f"((acc)[2]), "+f"((acc)[3])   \
        : "r"((a)[0]), "r"((a)[1]), "r"((a)[2]), "r"((a)[3]),              \
          "r"(b0), "r"(b1))

// ---------------------------------------------------------------------------
// k1: fold a: w1 = lin_w^T a1, c1 = lin_b.a1 (and 2)
// ---------------------------------------------------------------------------
__global__ void k1_prep(const float* __restrict__ lin_w,
                        const float* __restrict__ lin_b,
                        const float* __restrict__ a) {
    int f = threadIdx.x;
    __shared__ float sa1[E], sa2[E], red1[E], red2[E];
    float a1v = a[f], a2v = a[E + f];
    sa1[f] = a1v;
    sa2[f] = a2v;
    __syncthreads();
    float acc1 = 0.f, acc2 = 0.f;
#pragma unroll 8
    for (int e = 0; e < E; e++) {
        float lw = lin_w[e * F + f];
        acc1 += lw * sa1[e];
        acc2 += lw * sa2[e];
    }
    g_w1[f] = acc1;
    g_w2[f] = acc2;
    float lb = lin_b[f];
    red1[f] = lb * a1v;
    red2[f] = lb * a2v;
    __syncthreads();
    for (int s = 64; s > 0; s >>= 1) {
        if (f < s) {
            red1[f] += red1[f + s];
            red2[f] += red2[f + s];
        }
        __syncthreads();
    }
    if (f == 0) {
        g_c[0] = red1[0];
        g_c[1] = red2[0];
    }
}

// ---------------------------------------------------------------------------
// k2: s1/s2 row scores (exact fp32) + fused x -> fp16. One warp per row.
// ---------------------------------------------------------------------------
__global__ void k2_scores(const float* __restrict__ x) {
    int row = (blockIdx.x * blockDim.x + threadIdx.x) >> 5;
    int lane = threadIdx.x & 31;
    if (row >= B * K) return;
    float4 xv = ((const float4*)(x + (size_t)row * F))[lane];
    __half2 hx0 = __floats2half2_rn(xv.x, xv.y);
    __half2 hx1 = __floats2half2_rn(xv.z, xv.w);
    uint2 pk;
    pk.x = *(uint32_t*)&hx0;
    pk.y = *(uint32_t*)&hx1;
    *(uint2*)(g_xh + (size_t)row * F + lane * 4) = pk;

    float4 w1 = ((const float4*)g_w1)[lane];
    float4 w2 = ((const float4*)g_w2)[lane];
    float d1 = xv.x * w1.x + xv.y * w1.y + xv.z * w1.z + xv.w * w1.w;
    float d2 = xv.x * w2.x + xv.y * w2.y + xv.z * w2.z + xv.w * w2.w;
#pragma unroll
    for (int off = 16; off; off >>= 1) {
        d1 += __shfl_xor_sync(~0u, d1, off);
        d2 += __shfl_xor_sync(~0u, d2, off);
    }
    if (lane == 0) {
        g_s1[row] = d1 + g_c[0];
        g_s2[row] = d2 + g_c[1];
    }
}

// ---------------------------------------------------------------------------
// k2h: fp32 -> fp16 conversion (lin2_w only).
// ---------------------------------------------------------------------------
__global__ void k2h_half(const float* __restrict__ src, __half* __restrict__ dst, int n8) {
    int i = blockIdx.x * 256 + threadIdx.x;
    if (i >= n8) return;
    float4 a = ((const float4*)src)[2 * i];
    float4 b = ((const float4*)src)[2 * i + 1];
    __half2 h[4];
    h[0] = __floats2half2_rn(a.x, a.y);
    h[1] = __floats2half2_rn(a.z, a.w);
    h[2] = __floats2half2_rn(b.x, b.y);
    h[3] = __floats2half2_rn(b.z, b.w);
    ((uint4*)dst)[i] = *(uint4*)h;
}

// ---------------------------------------------------------------------------
// k3g: fused [softmax-numerator GEMM] + [lin2 GEMM], swizzled smem.
// 512 threads = 16 warps as 4(m) x 4(n); warp tile 32 x 32; 2 blocks/SM.
// ---------------------------------------------------------------------------
__global__ void __launch_bounds__(512, 2) k3g(const float* __restrict__ x,
                                              const float* __restrict__ bias) {
    extern __shared__ char sm[];
    const uint32_t sbase = smem_u32(sm);
    float* s2s = (float*)(sm + OFF_S2);
    float* s1s = (float*)(sm + OFF_S1);
    float* invs = (float*)(sm + OFF_INV);

    const int tid = threadIdx.x;
    const int wid = tid >> 5, lane = tid & 31;
    const int b = blockIdx.y;
    const int i0 = blockIdx.x * 128;
    const int warp_m = (wid >> 2) * 32;  // 0,32,64,96
    const int warp_n = (wid & 3) * 32;   // 0..96
    const int wn8 = warp_n >> 3;
    const int qr = lane >> 2, qc = lane & 3;
    const int lrow = (lane & 7) | (((lane >> 3) & 1) << 3);
    const int hi = lane >> 4;  // 0 or 1
    const int r7 = lane & 7;

    const float* Xb = x + (size_t)b * K * F;
    const __half* Xh = g_xh + (size_t)b * K * F;

    const int prow = tid >> 2;            // 0..127 (E row)
    const int pj0 = (tid & 3) * 16;       // j base within chunk (16 j each)
    const int pc16 = (tid & 3) * 2;       // 16B-col base
    const int jx = tid >> 3, cx = tid & 7;  // X staging coords (64 rows x 8)

    for (int j = tid; j < K; j += 512) s2s[j] = g_s2[b * K + j];
    if (tid < 128) s1s[tid] = g_s1[b * K + i0 + tid];
    __syncthreads();

    const float s1 = s1s[prow];
    float rsum = 0.f;

    float acc[2][4][4];
#pragma unroll
    for (int mt = 0; mt < 2; mt++)
#pragma unroll
        for (int nt = 0; nt < 4; nt++)
#pragma unroll
            for (int q = 0; q < 4; q++) acc[mt][nt][q] = 0.f;

#define STAGE_X(c, bi)                                                          \
    do {                                                                        \
        uint32_t xd = sbase + OFF_X + (bi) * XBUF;                              \
        _Pragma("unroll") for (int t = 0; t < 2; t++) {                         \
            int c16 = cx * 2 + t;                                               \
            cp16(xd + swzX(jx, c16),                                            \
                 Xh + (size_t)((c) * CH + jx) * F + c16 * 8);                   \
        }                                                                       \
        cp_commit();                                                            \
    } while (0)

#define COMPUTE_E(c, bi)                                                             \
    do {                                                                             \
        const float* brow = bias + (size_t)(i0 + prow) * K + (c) * CH + pj0;         \
        const float* s2p = s2s + (c) * CH + pj0;                                     \
        char* abase = sm + OFF_A + (bi) * ABUF;                                      \
        _Pragma("unroll") for (int t = 0; t < 2; t++) {                              \
            uint32_t hb[4];                                                          \
            _Pragma("unroll") for (int qq = 0; qq < 2; qq++) {                       \
                int q = t * 2 + qq;                                                  \
                float4 bv = *(const float4*)(brow + q * 4);                          \
                float4 s2v = *(const float4*)(s2p + q * 4);                          \
                float v, e0, e1, e2, e3;                                             \
                v = s1 + s2v.x; v = (v > 0.f ? v : ALPHA * v) + bv.x; e0 = __expf(v); \
                v = s1 + s2v.y; v = (v > 0.f ? v : ALPHA * v) + bv.y; e1 = __expf(v); \
                v = s1 + s2v.z; v = (v > 0.f ? v : ALPHA * v) + bv.z; e2 = __expf(v); \
                v = s1 + s2v.w; v = (v > 0.f ? v : ALPHA * v) + bv.w; e3 = __expf(v); \
                rsum += (e0 + e1) + (e2 + e3);                                       \
                __half2 p0 = __floats2half2_rn(e0, e1);                              \
                __half2 p1 = __floats2half2_rn(e2, e3);                              \
                hb[qq * 2] = *(uint32_t*)&p0;                                        \
                hb[qq * 2 + 1] = *(uint32_t*)&p1;                                    \
            }                                                                        \
            *(uint4*)(abase + swzA(prow, pc16 + t)) = *(uint4*)hb;                   \
        }                                                                            \
    } while (0)

    STAGE_X(0, 0);
    COMPUTE_E(0, 0);
    for (int c = 0; c < NCH3; c++) {
        int bi = c & 1;
        if (c + 1 < NCH3) {
            STAGE_X(c + 1, bi ^ 1);
            COMPUTE_E(c + 1, bi ^ 1);
            CP_WAIT(1);
        } else {
            CP_WAIT(0);
        }
        __syncthreads();
        uint32_t aA = sbase + OFF_A + bi * ABUF;
        uint32_t aX = sbase + OFF_X + bi * XBUF;
#pragma unroll
        for (int kk = 0; kk < 4; kk++) {
            int sA = ((kk * 2 + hi) ^ r7) & 7;
            uint32_t af[2][4];
#pragma unroll
            for (int mt = 0; mt < 2; mt++)
                ldsm4(af[mt], aA + (warp_m + mt * 16 + lrow) * 128 + (sA << 4));
            uint32_t bf[2][4];
#pragma unroll
            for (int ntp = 0; ntp < 2; ntp++) {
                int c16 = wn8 + 2 * ntp + hi;
                ldsm4t(bf[ntp], aX + swzX(kk * 16 + lrow, c16));
            }
#pragma unroll
            for (int mt = 0; mt < 2; mt++) {
                MMA_F16(acc[mt][0], af[mt], bf[0][0], bf[0][1]);
                MMA_F16(acc[mt][1], af[mt], bf[0][2], bf[0][3]);
                MMA_F16(acc[mt][2], af[mt], bf[1][0], bf[1][1]);
                MMA_F16(acc[mt][3], af[mt], bf[1][2], bf[1][3]);
            }
        }
        __syncthreads();
    }

    // ---- inv: 4 threads share a row ----
    float total = rsum + __shfl_xor_sync(~0u, rsum, 1);
    total += __shfl_xor_sync(~0u, total, 2);
    if ((tid & 3) == 0) {
        float iv = 1.0f / total;
        invs[prow] = iv;
        g_inv[b * K + i0 + prow] = iv;
    }
    __syncthreads();

    // ---- epilogue: h = acc*inv + x -> fp16 H-tile (OFF_X, pitch 256 swz) ----
#pragma unroll
    for (int mt = 0; mt < 2; mt++) {
        int lr = warp_m + mt * 16 + qr;
        float ivA = invs[lr];
        float ivB = invs[lr + 8];
        int r0 = i0 + lr;
#pragma unroll
        for (int nt = 0; nt < 4; nt++) {
            int fc = warp_n + nt * 8 + qc * 2;
            int c16 = wn8 + nt;
            float2 xv0 = *(const float2*)(Xb + (size_t)r0 * F + fc);
            float2 xv1 = *(const float2*)(Xb + (size_t)(r0 + 8) * F + fc);
            *(__half2*)(sm + OFF_X + swzX(lr, c16) + 4 * qc) =
                __floats2half2_rn(acc[mt][nt][0] * ivA + xv0.x, acc[mt][nt][1] * ivA + xv0.y);
            *(__half2*)(sm + OFF_X + swzX(lr + 8, c16) + 4 * qc) =
                __floats2half2_rn(acc[mt][nt][2] * ivB + xv1.x, acc[mt][nt][3] * ivB + xv1.y);
        }
    }

    // ---- stage W k-slice [128 o x 128 k] into OFF_A (pitch 256 swz) ----
    {
        int wrow = tid >> 2;
        int wc0 = (tid & 3) * 4;
        int vb = wrow < OUT2 ? 16 : 0;
        const __half* wsrc = g_wh + (size_t)(wrow < OUT2 ? wrow : 0) * K + i0;
#pragma unroll
        for (int t = 0; t < 4; t++) {
            int c16 = wc0 + t;
            cp16z(sbase + OFF_A + swzX(wrow, c16), wsrc + c16 * 8, vb);
        }
        cp_commit();
    }
    CP_WAIT(0);
    __syncthreads();

    // ---- phase 2: D[o][f] = W @ H  (M=128 o, N=128 f, K=128) ----
#pragma unroll
    for (int mt = 0; mt < 2; mt++)
#pragma unroll
        for (int nt = 0; nt < 4; nt++)
#pragma unroll
            for (int q = 0; q < 4; q++) acc[mt][nt][q] = 0.f;

#pragma unroll
    for (int kk = 0; kk < 8; kk++) {
        uint32_t af[2][4];
#pragma unroll
        for (int mt = 0; mt < 2; mt++)
            ldsm4(af[mt], sbase + OFF_A + swzX(warp_m + mt * 16 + lrow, kk * 2 + hi));
        uint32_t bf[2][4];
#pragma unroll
        for (int ntp = 0; ntp < 2; ntp++)
            ldsm4t(bf[ntp], sbase + OFF_X + swzX(kk * 16 + lrow, wn8 + 2 * ntp + hi));
#pragma unroll
        for (int mt = 0; mt < 2; mt++) {
            MMA_F16(acc[mt][0], af[mt], bf[0][0], bf[0][1]);
            MMA_F16(acc[mt][1], af[mt], bf[0][2], bf[0][3]);
            MMA_F16(acc[mt][2], af[mt], bf[1][0], bf[1][1]);
            MMA_F16(acc[mt][3], af[mt], bf[1][2], bf[1][3]);
        }
    }

    // ---- atomic accumulate into g_h2[b][f][o] ----
    float* h2b = g_h2 + (size_t)b * F * OUT2;
#pragma unroll
    for (int mt = 0; mt < 2; mt++) {
        int o0 = warp_m + mt * 16 + qr;
#pragma unroll
        for (int nt = 0; nt < 4; nt++) {
            int fc = warp_n + nt * 8 + qc * 2;
            if (o0 < OUT2) {
                atomicAdd(&h2b[(size_t)fc * OUT2 + o0], acc[mt][nt][0]);
                atomicAdd(&h2b[(size_t)(fc + 1) * OUT2 + o0], acc[mt][nt][1]);
            }
            if (o0 + 8 < OUT2) {
                atomicAdd(&h2b[(size_t)fc * OUT2 + o0 + 8], acc[mt][nt][2]);
                atomicAdd(&h2b[(size_t)(fc + 1) * OUT2 + o0 + 8], acc[mt][nt][3]);
            }
        }
    }
}

// ---------------------------------------------------------------------------
// k3w: stream attention = exp(leaky(s1+s2)+bias) * inv. Pure bandwidth.
// ---------------------------------------------------------------------------
__global__ void __launch_bounds__(256) k3w(const float* __restrict__ bias,
                                           float* __restrict__ attn) {
    __shared__ float s2s[K];
    int b = blockIdx.y;
    int tid = threadIdx.x, warp = tid >> 5, lane = tid & 31;
    for (int j = tid; j < K; j += 256) s2s[j] = g_s2[b * K + j];
    __syncthreads();
    int gi = blockIdx.x * 8 + warp;
    float s1 = g_s1[b * K + gi];
    float iv = g_inv[b * K + gi];
    const float4* brow = (const float4*)(bias + (size_t)gi * K);
    const float4* s2s4 = (const float4*)s2s;
    float4* arow = (float4*)(attn + ((size_t)(b * K + gi)) * K);
#pragma unroll
    for (int t = 0; t < 8; t++) {
        int j4 = lane + t * 32;
        float4 bv = brow[j4];
        float4 s2v = s2s4[j4];
        float v;
        float4 p;
        v = s1 + s2v.x; v = (v > 0.f ? v : ALPHA * v) + bv.x; p.x = __expf(v) * iv;
        v = s1 + s2v.y; v = (v > 0.f ? v : ALPHA * v) + bv.y; p.y = __expf(v) * iv;
        v = s1 + s2v.z; v = (v > 0.f ? v : ALPHA * v) + bv.z; p.z = __expf(v) * iv;
        v = s1 + s2v.w; v = (v > 0.f ? v : ALPHA * v) + bv.w; p.w = __expf(v) * iv;
        arow[j4] = p;
    }
}

// ---------------------------------------------------------------------------
// k5: out = relu(g_h2 + lin2_b)
// ---------------------------------------------------------------------------
__global__ void k5_out(const float* __restrict__ lin2_b, float* __restrict__ out) {
    int i = blockIdx.x * 256 + threadIdx.x;
    if (i >= B * F * OUT2) return;
    float v = g_h2[i] + lin2_b[i % OUT2];
    out[i] = v > 0.f ? v : 0.f;
}

// ---------------------------------------------------------------------------
extern "C" void kernel_launch(void* const* d_in, const int* in_sizes, int n_in,
                              void* d_out, int out_size) {
    const float* x      = (const float*)d_in[0];
    const float* lin_w  = (const float*)d_in[1];
    const float* lin_b  = (const float*)d_in[2];
    const float* a      = (const float*)d_in[3];
    const float* bias   = (const float*)d_in[4];
    const float* lin2_w = (const float*)d_in[5];
    const float* lin2_b = (const float*)d_in[6];
    float* out = (float*)d_out;
    float* out_h2 = out;                           // (B,F,OUT2)
    float* out_attn = out + (size_t)B * F * OUT2;  // (B,K,K)

    cudaFuncSetAttribute(k3g, cudaFuncAttributeMaxDynamicSharedMemorySize, SMEM_K3G);

    void* wh = nullptr;
    void* h2 = nullptr;
    cudaGetSymbolAddress(&wh, g_wh);
    cudaGetSymbolAddress(&h2, g_h2);

    cudaMemsetAsync(h2, 0, sizeof(float) * B * F * OUT2);
    k1_prep<<<1, 128>>>(lin_w, lin_b, a);
    k2_scores<<<(B * K) / 8, 256>>>(x);
    k2h_half<<<(OUT2 * K / 8 + 255) / 256, 256>>>(lin2_w, (__half*)wh, OUT2 * K / 8);
    k3g<<<dim3(K / 128, B), 512, SMEM_K3G>>>(x, bias);
    k3w<<<dim3(K / 8, B), 256>>>(bias, out_attn);
    k5_out<<<(B * F * OUT2 + 255) / 256, 256>>>(lin2_b, out_h2);
}